// round 6
// baseline (speedup 1.0000x reference)
#include <cuda_runtime.h>
#include <math.h>

// Problem constants
#define NN 50000          // nodes
#define NE 500000         // original edges
#define ET (NE + NN)      // edges + self loops = 550000
#define D1 256            // layer1 out (4 heads x 64)
#define C2 64
#define IND 128

typedef unsigned long long ull;

// ---------------- device scratch (static, no allocation) ----------------
__device__ float  g_h1[NN * D1];        // layer1 projected features
__device__ float  g_out1[NN * D1];      // layer1 aggregated+elu output
__device__ float  g_h2[NN * C2];        // layer2 projected features
__device__ float  g_ssrc1[NN * 4];
__device__ float  g_sdst1[NN * 4];
__device__ float  g_ssrc2[NN];
__device__ float  g_sdst2[NN];
__device__ float4 g_alpha1[ET];
__device__ float  g_alpha2[ET];
__device__ float  g_loop[NN];
__device__ __align__(16) float g_eproj[8];   // [0..3]=layer1 heads, [4]=layer2
// CSR
__device__ int    g_deg[NN];
__device__ int    g_off[NN + 1];
__device__ int    g_cur[NN];
__device__ int    g_srcs[ET];
__device__ float  g_eattr[ET];          // edge attr (loop attr for self loops)
__device__ float  g_sum[NN];

// ---------------- f32x2 packed math helpers ----------------
__device__ __forceinline__ ull pack2(float lo, float hi) {
    ull r;
    asm("mov.b64 %0, {%1, %2};" : "=l"(r) : "f"(lo), "f"(hi));
    return r;
}
__device__ __forceinline__ void fma2(ull& d, ull a, ull b) {
    asm("fma.rn.f32x2 %0, %1, %2, %0;" : "+l"(d) : "l"(a), "l"(b));
}
__device__ __forceinline__ float2 unpack2(ull v) {
    float2 r;
    asm("mov.b64 {%0, %1}, %2;" : "=f"(r.x), "=f"(r.y) : "l"(v));
    return r;
}

// ---------------- init: deg=1 (self loop), sum=0, eproj scalars ----------------
__global__ void k_init(const float* __restrict__ We1, const float* __restrict__ ae1,
                       const float* __restrict__ We2, const float* __restrict__ ae2) {
    int i = blockIdx.x * blockDim.x + threadIdx.x;
    if (i < NN) { g_deg[i] = 1; g_sum[i] = 0.f; }
    if (blockIdx.x == 0) {
        __shared__ float sm[256];
        int t = threadIdx.x;
        sm[t] = We1[t] * ae1[t];
        __syncthreads();
        if (t < 4) {
            float s = 0.f;
            for (int j = 0; j < 64; j++) s += sm[t * 64 + j];
            g_eproj[t] = s;
        }
        __syncthreads();
        if (t < 64) sm[t] = We2[t] * ae2[t];
        __syncthreads();
        if (t == 0) {
            float s = 0.f;
            for (int j = 0; j < 64; j++) s += sm[j];
            g_eproj[4] = s;
        }
    }
}

__global__ void k_hist(const int* __restrict__ dst, const float* __restrict__ ea) {
    int e = blockIdx.x * blockDim.x + threadIdx.x;
    if (e >= NE) return;
    int d = dst[e];
    atomicAdd(&g_deg[d], 1);
    atomicAdd(&g_sum[d], ea[e]);
}

// single block 1024 threads: exclusive scan deg->off/cur, and loop attr
__global__ void k_scan() {
    __shared__ int part[1024];
    int t = threadIdx.x;
    const int CH = 49;                        // 1024*49 = 50176 >= NN
    int base = t * CH;
    int s = 0;
    for (int i = 0; i < CH; i++) {
        int idx = base + i;
        if (idx < NN) s += g_deg[idx];
    }
    part[t] = s;
    __syncthreads();
    for (int off = 1; off < 1024; off <<= 1) {
        int v = (t >= off) ? part[t - off] : 0;
        __syncthreads();
        part[t] += v;
        __syncthreads();
    }
    int run = part[t] - s;                    // exclusive prefix
    for (int i = 0; i < CH; i++) {
        int idx = base + i;
        if (idx < NN) {
            int d = g_deg[idx];
            g_off[idx] = run; g_cur[idx] = run;
            g_loop[idx] = g_sum[idx] / fmaxf((float)(d - 1), 1.f);
            run += d;
        }
    }
    if (t == 1023) g_off[NN] = part[1023];
}

__global__ void k_fill(const int* __restrict__ src, const int* __restrict__ dst,
                       const float* __restrict__ ea) {
    int e = blockIdx.x * blockDim.x + threadIdx.x;
    if (e >= ET) return;
    int s, d; float a;
    if (e < NE) { s = src[e]; d = dst[e]; a = ea[e]; }
    else { s = e - NE; d = s; a = g_loop[s]; }
    int pos = atomicAdd(&g_cur[d], 1);
    g_srcs[pos] = s;
    g_eattr[pos] = a;
}

// ---------------- GEMMs (packed f32x2 FMA) ----------------

// GEMM1: h1 = x @ W1. Block: 32 nodes x 256 cols; thread: 8 nodes x 4 cols (2 col-pairs).
__global__ void __launch_bounds__(256) k_gemm1(const float* __restrict__ x,
                                               const float* __restrict__ W1) {
    __shared__ __align__(16) float xs[32 * IND];     // 16KB
    int t = threadIdx.x;
    int tx = t & 63, ty = t >> 6;
    int nodeBase = blockIdx.x * 32;
    const float4* xg = (const float4*)x;
    float4* xs4 = (float4*)xs;
#pragma unroll
    for (int i = 0; i < 4; i++) {
        int idx = i * 256 + t;
        int gidx = nodeBase * 32 + idx;
        xs4[idx] = (gidx < NN * 32) ? xg[gidx] : make_float4(0.f, 0.f, 0.f, 0.f);
    }
    __syncthreads();
    ull acc[16];
#pragma unroll
    for (int i = 0; i < 16; i++) acc[i] = 0ull;
    const float4* __restrict__ W4 = (const float4*)W1;
    const float* xrow = xs + ty * 8 * IND;
#pragma unroll 2
    for (int k = 0; k < IND; k++) {
        float4 w = W4[k * 64 + tx];
        ull wlo = pack2(w.x, w.y);
        ull whi = pack2(w.z, w.w);
#pragma unroll
        for (int i = 0; i < 8; i++) {
            float xv = xrow[i * IND + k];
            ull xp = pack2(xv, xv);
            fma2(acc[i * 2 + 0], xp, wlo);
            fma2(acc[i * 2 + 1], xp, whi);
        }
    }
#pragma unroll
    for (int i = 0; i < 8; i++) {
        int node = nodeBase + ty * 8 + i;
        if (node < NN) {
            float2 lo = unpack2(acc[i * 2]), hi = unpack2(acc[i * 2 + 1]);
            ((float4*)g_h1)[node * 64 + tx] = make_float4(lo.x, lo.y, hi.x, hi.y);
        }
    }
}

// GEMM2: h2 = out1 @ W2. Block: 48 nodes x 64 cols; thread: 3 nodes x 4 cols.
__global__ void __launch_bounds__(256) k_gemm2(const float* __restrict__ W2) {
    __shared__ __align__(16) float xs[48 * D1];      // 48KB
    int t = threadIdx.x;
    int tx = t & 15, ty = t >> 4;
    int nodeBase = blockIdx.x * 48;
    const float4* xg = (const float4*)g_out1;
    float4* xs4 = (float4*)xs;
#pragma unroll
    for (int i = 0; i < 12; i++) {
        int idx = i * 256 + t;
        int gidx = nodeBase * 64 + idx;
        xs4[idx] = (gidx < NN * 64) ? xg[gidx] : make_float4(0.f, 0.f, 0.f, 0.f);
    }
    __syncthreads();
    ull acc[6];
#pragma unroll
    for (int i = 0; i < 6; i++) acc[i] = 0ull;
    const float4* __restrict__ W4 = (const float4*)W2;
    const float* xrow = xs + ty * 3 * D1;
#pragma unroll 2
    for (int k = 0; k < D1; k++) {
        float4 w = W4[k * 16 + tx];
        ull wlo = pack2(w.x, w.y);
        ull whi = pack2(w.z, w.w);
#pragma unroll
        for (int i = 0; i < 3; i++) {
            float xv = xrow[i * D1 + k];
            ull xp = pack2(xv, xv);
            fma2(acc[i * 2 + 0], xp, wlo);
            fma2(acc[i * 2 + 1], xp, whi);
        }
    }
#pragma unroll
    for (int i = 0; i < 3; i++) {
        int node = nodeBase + ty * 3 + i;
        if (node < NN) {
            float2 lo = unpack2(acc[i * 2]), hi = unpack2(acc[i * 2 + 1]);
            ((float4*)g_h2)[node * 16 + tx] = make_float4(lo.x, lo.y, hi.x, hi.y);
        }
    }
}

// ---------------- attention score dots ----------------

__global__ void k_score1(const float* __restrict__ as1, const float* __restrict__ ad1) {
    int n = (blockIdx.x * blockDim.x + threadIdx.x) >> 5;
    int lane = threadIdx.x & 31;
    if (n >= NN) return;
    const float4* row = (const float4*)g_h1 + n * 64;
    float4 v0 = row[lane * 2], v1 = row[lane * 2 + 1];
    float4 a0 = ((const float4*)as1)[lane * 2], a1 = ((const float4*)as1)[lane * 2 + 1];
    float4 d0 = ((const float4*)ad1)[lane * 2], d1 = ((const float4*)ad1)[lane * 2 + 1];
    float ps = v0.x * a0.x + v0.y * a0.y + v0.z * a0.z + v0.w * a0.w
             + v1.x * a1.x + v1.y * a1.y + v1.z * a1.z + v1.w * a1.w;
    float pd = v0.x * d0.x + v0.y * d0.y + v0.z * d0.z + v0.w * d0.w
             + v1.x * d1.x + v1.y * d1.y + v1.z * d1.z + v1.w * d1.w;
#pragma unroll
    for (int off = 4; off; off >>= 1) {
        ps += __shfl_xor_sync(0xffffffffu, ps, off);
        pd += __shfl_xor_sync(0xffffffffu, pd, off);
    }
    if ((lane & 7) == 0) {
        int h = lane >> 3;
        g_ssrc1[n * 4 + h] = ps;
        g_sdst1[n * 4 + h] = pd;
    }
}

__global__ void k_score2(const float* __restrict__ as2, const float* __restrict__ ad2) {
    int n = (blockIdx.x * blockDim.x + threadIdx.x) >> 5;
    int lane = threadIdx.x & 31;
    if (n >= NN) return;
    float2 v = ((const float2*)(g_h2 + n * 64))[lane];
    float2 a = ((const float2*)as2)[lane];
    float2 d = ((const float2*)ad2)[lane];
    float ps = v.x * a.x + v.y * a.y;
    float pd = v.x * d.x + v.y * d.y;
#pragma unroll
    for (int off = 16; off; off >>= 1) {
        ps += __shfl_xor_sync(0xffffffffu, ps, off);
        pd += __shfl_xor_sync(0xffffffffu, pd, off);
    }
    if (lane == 0) { g_ssrc2[n] = ps; g_sdst2[n] = pd; }
}

// ---------------- fused online-softmax + aggregation ----------------

// warp per dst node, layer1 (4 heads, 256 feature cols)
__global__ void __launch_bounds__(256) k_agg1(const float* __restrict__ b1) {
    int n = (blockIdx.x * blockDim.x + threadIdx.x) >> 5;
    int lane = threadIdx.x & 31;
    if (n >= NN) return;
    int o0 = g_off[n], deg = g_off[n + 1] - o0;
    float4 ep = *((const float4*)g_eproj);
    float4 sd = ((const float4*)g_sdst1)[n];

    // pass A: alpha (leaky relu) + online max/sum
    float4 mx = make_float4(-1e30f, -1e30f, -1e30f, -1e30f);
    float4 se = make_float4(0.f, 0.f, 0.f, 0.f);
    for (int i = lane; i < deg; i += 32) {
        int p = o0 + i;
        float a = g_eattr[p];
        int s = g_srcs[p];
        float4 ss = ((const float4*)g_ssrc1)[s];
        float4 al;
        al.x = ss.x + sd.x + a * ep.x;
        al.y = ss.y + sd.y + a * ep.y;
        al.z = ss.z + sd.z + a * ep.z;
        al.w = ss.w + sd.w + a * ep.w;
        al.x = al.x > 0.f ? al.x : 0.2f * al.x;
        al.y = al.y > 0.f ? al.y : 0.2f * al.y;
        al.z = al.z > 0.f ? al.z : 0.2f * al.z;
        al.w = al.w > 0.f ? al.w : 0.2f * al.w;
        g_alpha1[p] = al;
        float nm;
        nm = fmaxf(mx.x, al.x); se.x = se.x * __expf(mx.x - nm) + __expf(al.x - nm); mx.x = nm;
        nm = fmaxf(mx.y, al.y); se.y = se.y * __expf(mx.y - nm) + __expf(al.y - nm); mx.y = nm;
        nm = fmaxf(mx.z, al.z); se.z = se.z * __expf(mx.z - nm) + __expf(al.z - nm); mx.z = nm;
        nm = fmaxf(mx.w, al.w); se.w = se.w * __expf(mx.w - nm) + __expf(al.w - nm); mx.w = nm;
    }
#pragma unroll
    for (int off = 16; off; off >>= 1) {
        float om, os, nm;
        om = __shfl_xor_sync(0xffffffffu, mx.x, off); os = __shfl_xor_sync(0xffffffffu, se.x, off);
        nm = fmaxf(mx.x, om); se.x = se.x * __expf(mx.x - nm) + os * __expf(om - nm); mx.x = nm;
        om = __shfl_xor_sync(0xffffffffu, mx.y, off); os = __shfl_xor_sync(0xffffffffu, se.y, off);
        nm = fmaxf(mx.y, om); se.y = se.y * __expf(mx.y - nm) + os * __expf(om - nm); mx.y = nm;
        om = __shfl_xor_sync(0xffffffffu, mx.z, off); os = __shfl_xor_sync(0xffffffffu, se.z, off);
        nm = fmaxf(mx.z, om); se.z = se.z * __expf(mx.z - nm) + os * __expf(om - nm); mx.z = nm;
        om = __shfl_xor_sync(0xffffffffu, mx.w, off); os = __shfl_xor_sync(0xffffffffu, se.w, off);
        nm = fmaxf(mx.w, om); se.w = se.w * __expf(mx.w - nm) + os * __expf(om - nm); mx.w = nm;
    }
    float4 wv;
    wv.x = 1.f / (se.x + 1e-16f); wv.y = 1.f / (se.y + 1e-16f);
    wv.z = 1.f / (se.z + 1e-16f); wv.w = 1.f / (se.w + 1e-16f);
    __syncwarp();

    // pass B: coalesced gather-accumulate; lane covers cols [lane*8, lane*8+8)
    int h = lane >> 3;
    float mxh = (h == 0) ? mx.x : (h == 1) ? mx.y : (h == 2) ? mx.z : mx.w;
    float wvh = (h == 0) ? wv.x : (h == 1) ? wv.y : (h == 2) ? wv.z : wv.w;
    float4 acc0 = make_float4(0.f, 0.f, 0.f, 0.f);
    float4 acc1 = make_float4(0.f, 0.f, 0.f, 0.f);
    // prefetch pipeline
    float4 al_n; int s_n;
    {
        int p = o0;
        al_n = g_alpha1[p];
        s_n = g_srcs[p];
    }
    for (int i = 0; i < deg; i++) {
        float4 al = al_n;
        int s = s_n;
        if (i + 1 < deg) {
            int p = o0 + i + 1;
            al_n = g_alpha1[p];
            s_n = g_srcs[p];
        }
        float alh = (h == 0) ? al.x : (h == 1) ? al.y : (h == 2) ? al.z : al.w;
        float aw = __expf(alh - mxh) * wvh;
        const float4* row = (const float4*)g_h1 + s * 64;
        float4 v0 = row[lane * 2], v1 = row[lane * 2 + 1];
        acc0.x += aw * v0.x; acc0.y += aw * v0.y; acc0.z += aw * v0.z; acc0.w += aw * v0.w;
        acc1.x += aw * v1.x; acc1.y += aw * v1.y; acc1.z += aw * v1.z; acc1.w += aw * v1.w;
    }
    float4 bb0 = ((const float4*)b1)[lane * 2], bb1 = ((const float4*)b1)[lane * 2 + 1];
    acc0.x += bb0.x; acc0.y += bb0.y; acc0.z += bb0.z; acc0.w += bb0.w;
    acc1.x += bb1.x; acc1.y += bb1.y; acc1.z += bb1.z; acc1.w += bb1.w;
    acc0.x = acc0.x > 0.f ? acc0.x : (__expf(acc0.x) - 1.f);
    acc0.y = acc0.y > 0.f ? acc0.y : (__expf(acc0.y) - 1.f);
    acc0.z = acc0.z > 0.f ? acc0.z : (__expf(acc0.z) - 1.f);
    acc0.w = acc0.w > 0.f ? acc0.w : (__expf(acc0.w) - 1.f);
    acc1.x = acc1.x > 0.f ? acc1.x : (__expf(acc1.x) - 1.f);
    acc1.y = acc1.y > 0.f ? acc1.y : (__expf(acc1.y) - 1.f);
    acc1.z = acc1.z > 0.f ? acc1.z : (__expf(acc1.z) - 1.f);
    acc1.w = acc1.w > 0.f ? acc1.w : (__expf(acc1.w) - 1.f);
    float4* orow = (float4*)g_out1 + n * 64;
    orow[lane * 2] = acc0;
    orow[lane * 2 + 1] = acc1;
}

// warp per dst node, layer2 (1 head, 64 cols) -> final output + bias2
__global__ void __launch_bounds__(256) k_agg2(const float* __restrict__ b2,
                                              float* __restrict__ dout) {
    int n = (blockIdx.x * blockDim.x + threadIdx.x) >> 5;
    int lane = threadIdx.x & 31;
    if (n >= NN) return;
    int o0 = g_off[n], deg = g_off[n + 1] - o0;
    float ep = g_eproj[4];
    float sdn = g_sdst2[n];

    float mx = -1e30f, se = 0.f;
    for (int i = lane; i < deg; i += 32) {
        int p = o0 + i;
        float a = g_eattr[p];
        int s = g_srcs[p];
        float al = g_ssrc2[s] + sdn + a * ep;
        al = al > 0.f ? al : 0.2f * al;
        g_alpha2[p] = al;
        float nm = fmaxf(mx, al);
        se = se * __expf(mx - nm) + __expf(al - nm);
        mx = nm;
    }
#pragma unroll
    for (int off = 16; off; off >>= 1) {
        float om = __shfl_xor_sync(0xffffffffu, mx, off);
        float os = __shfl_xor_sync(0xffffffffu, se, off);
        float nm = fmaxf(mx, om);
        se = se * __expf(mx - nm) + os * __expf(om - nm);
        mx = nm;
    }
    float w = 1.f / (se + 1e-16f);
    __syncwarp();

    float2 acc = make_float2(0.f, 0.f);
    float al_n; int s_n;
    {
        al_n = g_alpha2[o0];
        s_n = g_srcs[o0];
    }
    for (int i = 0; i < deg; i++) {
        float al = al_n;
        int s = s_n;
        if (i + 1 < deg) {
            al_n = g_alpha2[o0 + i + 1];
            s_n = g_srcs[o0 + i + 1];
        }
        float aw = __expf(al - mx) * w;
        float2 v = ((const float2*)(g_h2 + s * 64))[lane];
        acc.x += aw * v.x;
        acc.y += aw * v.y;
    }
    float2 bb = ((const float2*)b2)[lane];
    ((float2*)(dout + n * 64))[lane] = make_float2(acc.x + bb.x, acc.y + bb.y);
}

// ---------------- launch ----------------
extern "C" void kernel_launch(void* const* d_in, const int* in_sizes, int n_in,
                              void* d_out, int out_size) {
    const float* x   = (const float*)d_in[0];
    const int*   ei  = (const int*)d_in[1];
    const float* ea  = (const float*)d_in[2];
    const float* W1  = (const float*)d_in[3];
    const float* We1 = (const float*)d_in[4];
    const float* as1 = (const float*)d_in[5];
    const float* ad1 = (const float*)d_in[6];
    const float* ae1 = (const float*)d_in[7];
    const float* b1  = (const float*)d_in[8];
    const float* W2  = (const float*)d_in[9];
    const float* We2 = (const float*)d_in[10];
    const float* as2 = (const float*)d_in[11];
    const float* ad2 = (const float*)d_in[12];
    const float* ae2 = (const float*)d_in[13];
    const float* b2  = (const float*)d_in[14];
    float* dout = (float*)d_out;

    const int* src = ei;
    const int* dst = ei + NE;

    const int WPB = 8;                         // warps (nodes) per 256-thread block
    const int NB  = (NN + WPB - 1) / WPB;      // 6250

    k_init<<<(NN + 255) / 256, 256>>>(We1, ae1, We2, ae2);
    k_hist<<<(NE + 255) / 256, 256>>>(dst, ea);
    k_scan<<<1, 1024>>>();
    k_fill<<<(ET + 255) / 256, 256>>>(src, dst, ea);

    k_gemm1<<<(NN + 31) / 32, 256>>>(x, W1);
    k_score1<<<NB, 256>>>(as1, ad1);
    k_agg1<<<NB, 256>>>(b1);

    k_gemm2<<<(NN + 47) / 48, 256>>>(W2);
    k_score2<<<NB, 256>>>(as2, ad2);
    k_agg2<<<NB, 256>>>(b2, dout);
}

// round 7
// speedup vs baseline: 1.0752x; 1.0752x over previous
#include <cuda_runtime.h>
#include <math.h>

// Problem constants
#define NN 50000          // nodes
#define NE 500000         // original edges
#define ET (NE + NN)      // edges + self loops = 550000
#define D1 256            // layer1 out (4 heads x 64)
#define C2 64
#define IND 128

// ---------------- device scratch (static, no allocation) ----------------
__device__ float  g_h1[NN * D1];        // layer1 projected features
__device__ float  g_out1[NN * D1];      // layer1 aggregated+elu output
__device__ float  g_h2[NN * C2];        // layer2 projected features
__device__ float  g_ssrc1[NN * 4];
__device__ float  g_sdst1[NN * 4];
__device__ float  g_ssrc2[NN];
__device__ float  g_sdst2[NN];
__device__ float4 g_alpha1[ET];
__device__ float  g_alpha2[ET];
__device__ float  g_loop[NN];
__device__ __align__(16) float g_eproj[8];   // [0..3]=layer1 heads, [4]=layer2
// CSR
__device__ int    g_deg[NN];
__device__ int    g_off[NN + 1];
__device__ int    g_cur[NN];
__device__ int    g_srcs[ET];
__device__ float  g_eattr[ET];          // edge attr (loop attr for self loops)
__device__ float  g_sum[NN];

// ---------------- init: deg=1 (self loop), sum=0, eproj scalars ----------------
__global__ void k_init(const float* __restrict__ We1, const float* __restrict__ ae1,
                       const float* __restrict__ We2, const float* __restrict__ ae2) {
    int i = blockIdx.x * blockDim.x + threadIdx.x;
    if (i < NN) { g_deg[i] = 1; g_sum[i] = 0.f; }
    if (blockIdx.x == 0) {
        __shared__ float sm[256];
        int t = threadIdx.x;
        sm[t] = We1[t] * ae1[t];
        __syncthreads();
        if (t < 4) {
            float s = 0.f;
            for (int j = 0; j < 64; j++) s += sm[t * 64 + j];
            g_eproj[t] = s;
        }
        __syncthreads();
        if (t < 64) sm[t] = We2[t] * ae2[t];
        __syncthreads();
        if (t == 0) {
            float s = 0.f;
            for (int j = 0; j < 64; j++) s += sm[j];
            g_eproj[4] = s;
        }
    }
}

__global__ void k_hist(const int* __restrict__ dst, const float* __restrict__ ea) {
    int e = blockIdx.x * blockDim.x + threadIdx.x;
    if (e >= NE) return;
    int d = dst[e];
    atomicAdd(&g_deg[d], 1);
    atomicAdd(&g_sum[d], ea[e]);
}

// single block 1024 threads: exclusive scan deg->off/cur, and loop attr
__global__ void k_scan() {
    __shared__ int part[1024];
    int t = threadIdx.x;
    const int CH = 49;                        // 1024*49 = 50176 >= NN
    int base = t * CH;
    int s = 0;
    for (int i = 0; i < CH; i++) {
        int idx = base + i;
        if (idx < NN) s += g_deg[idx];
    }
    part[t] = s;
    __syncthreads();
    for (int off = 1; off < 1024; off <<= 1) {
        int v = (t >= off) ? part[t - off] : 0;
        __syncthreads();
        part[t] += v;
        __syncthreads();
    }
    int run = part[t] - s;                    // exclusive prefix
    for (int i = 0; i < CH; i++) {
        int idx = base + i;
        if (idx < NN) {
            int d = g_deg[idx];
            g_off[idx] = run; g_cur[idx] = run;
            g_loop[idx] = g_sum[idx] / fmaxf((float)(d - 1), 1.f);
            run += d;
        }
    }
    if (t == 1023) g_off[NN] = part[1023];
}

__global__ void k_fill(const int* __restrict__ src, const int* __restrict__ dst,
                       const float* __restrict__ ea) {
    int e = blockIdx.x * blockDim.x + threadIdx.x;
    if (e >= ET) return;
    int s, d; float a;
    if (e < NE) { s = src[e]; d = dst[e]; a = ea[e]; }
    else { s = e - NE; d = s; a = g_loop[s]; }
    int pos = atomicAdd(&g_cur[d], 1);
    g_srcs[pos] = s;
    g_eattr[pos] = a;
}

// ---------------- GEMMs (plain FFMA, scores fused into epilogue) ----------------

// GEMM1: h1 = x @ W1. Block: 32 nodes x 256 cols; thread: 8 nodes x 4 cols.
// Epilogue: per-(node,head) attention dots reduced across 16 lanes.
__global__ void __launch_bounds__(256) k_gemm1(const float* __restrict__ x,
                                               const float* __restrict__ W1,
                                               const float* __restrict__ as1,
                                               const float* __restrict__ ad1) {
    __shared__ __align__(16) float xs[32 * IND];     // 16KB
    int t = threadIdx.x;
    int tx = t & 63, ty = t >> 6;
    int nodeBase = blockIdx.x * 32;
    const float4* xg = (const float4*)x;
    float4* xs4 = (float4*)xs;
#pragma unroll
    for (int i = 0; i < 4; i++) {
        int idx = i * 256 + t;
        int gidx = nodeBase * 32 + idx;
        xs4[idx] = (gidx < NN * 32) ? xg[gidx] : make_float4(0.f, 0.f, 0.f, 0.f);
    }
    __syncthreads();
    float4 acc[8];
#pragma unroll
    for (int i = 0; i < 8; i++) acc[i] = make_float4(0.f, 0.f, 0.f, 0.f);
    const float4* __restrict__ W4 = (const float4*)W1;
    const float* xrow = xs + ty * 8 * IND;
#pragma unroll 4
    for (int k = 0; k < IND; k++) {
        float4 w = W4[k * 64 + tx];
#pragma unroll
        for (int i = 0; i < 8; i++) {
            float xv = xrow[i * IND + k];
            acc[i].x += xv * w.x; acc[i].y += xv * w.y;
            acc[i].z += xv * w.z; acc[i].w += xv * w.w;
        }
    }
    // store h1
#pragma unroll
    for (int i = 0; i < 8; i++) {
        int node = nodeBase + ty * 8 + i;
        if (node < NN) ((float4*)g_h1)[node * 64 + tx] = acc[i];
    }
    // fused score epilogue: head h = tx>>4 owns float4 cols [16h,16h+16)
    float4 av = ((const float4*)as1)[tx];
    float4 dv = ((const float4*)ad1)[tx];
    float ps[8], pd[8];
#pragma unroll
    for (int i = 0; i < 8; i++) {
        ps[i] = acc[i].x * av.x + acc[i].y * av.y + acc[i].z * av.z + acc[i].w * av.w;
        pd[i] = acc[i].x * dv.x + acc[i].y * dv.y + acc[i].z * dv.z + acc[i].w * dv.w;
    }
#pragma unroll
    for (int off = 8; off; off >>= 1) {
#pragma unroll
        for (int i = 0; i < 8; i++) {
            ps[i] += __shfl_xor_sync(0xffffffffu, ps[i], off);
            pd[i] += __shfl_xor_sync(0xffffffffu, pd[i], off);
        }
    }
    if ((tx & 15) == 0) {
        int h = tx >> 4;
#pragma unroll
        for (int i = 0; i < 8; i++) {
            int node = nodeBase + ty * 8 + i;
            if (node < NN) {
                g_ssrc1[node * 4 + h] = ps[i];
                g_sdst1[node * 4 + h] = pd[i];
            }
        }
    }
}

// GEMM2: h2 = out1 @ W2. Block: 48 nodes x 64 cols; thread: 3 nodes x 4 cols.
// Epilogue: single-head attention dots reduced across 16 lanes.
__global__ void __launch_bounds__(256) k_gemm2(const float* __restrict__ W2,
                                               const float* __restrict__ as2,
                                               const float* __restrict__ ad2) {
    __shared__ __align__(16) float xs[48 * D1];      // 48KB
    int t = threadIdx.x;
    int tx = t & 15, ty = t >> 4;
    int nodeBase = blockIdx.x * 48;
    const float4* xg = (const float4*)g_out1;
    float4* xs4 = (float4*)xs;
#pragma unroll
    for (int i = 0; i < 12; i++) {
        int idx = i * 256 + t;
        int gidx = nodeBase * 64 + idx;
        xs4[idx] = (gidx < NN * 64) ? xg[gidx] : make_float4(0.f, 0.f, 0.f, 0.f);
    }
    __syncthreads();
    float4 acc[3];
#pragma unroll
    for (int i = 0; i < 3; i++) acc[i] = make_float4(0.f, 0.f, 0.f, 0.f);
    const float4* __restrict__ W4 = (const float4*)W2;
    const float* xrow = xs + ty * 3 * D1;
#pragma unroll 4
    for (int k = 0; k < D1; k++) {
        float4 w = W4[k * 16 + tx];
#pragma unroll
        for (int i = 0; i < 3; i++) {
            float xv = xrow[i * D1 + k];
            acc[i].x += xv * w.x; acc[i].y += xv * w.y;
            acc[i].z += xv * w.z; acc[i].w += xv * w.w;
        }
    }
#pragma unroll
    for (int i = 0; i < 3; i++) {
        int node = nodeBase + ty * 3 + i;
        if (node < NN) ((float4*)g_h2)[node * 16 + tx] = acc[i];
    }
    float4 av = ((const float4*)as2)[tx];
    float4 dv = ((const float4*)ad2)[tx];
    float ps[3], pd[3];
#pragma unroll
    for (int i = 0; i < 3; i++) {
        ps[i] = acc[i].x * av.x + acc[i].y * av.y + acc[i].z * av.z + acc[i].w * av.w;
        pd[i] = acc[i].x * dv.x + acc[i].y * dv.y + acc[i].z * dv.z + acc[i].w * dv.w;
    }
#pragma unroll
    for (int off = 8; off; off >>= 1) {
#pragma unroll
        for (int i = 0; i < 3; i++) {
            ps[i] += __shfl_xor_sync(0xffffffffu, ps[i], off);
            pd[i] += __shfl_xor_sync(0xffffffffu, pd[i], off);
        }
    }
    if (tx == 0) {
#pragma unroll
        for (int i = 0; i < 3; i++) {
            int node = nodeBase + ty * 3 + i;
            if (node < NN) { g_ssrc2[node] = ps[i]; g_sdst2[node] = pd[i]; }
        }
    }
}

// ---------------- fused softmax + aggregation ----------------

// warp per dst node, layer1 (4 heads, 256 feature cols)
__global__ void __launch_bounds__(256) k_agg1(const float* __restrict__ b1) {
    int n = (blockIdx.x * blockDim.x + threadIdx.x) >> 5;
    int lane = threadIdx.x & 31;
    if (n >= NN) return;
    int o0 = g_off[n], deg = g_off[n + 1] - o0;
    float4 ep = *((const float4*)g_eproj);
    float4 sd = ((const float4*)g_sdst1)[n];

    // pass A: alpha (leaky relu), per-head max
    float4 mx = make_float4(-1e30f, -1e30f, -1e30f, -1e30f);
    for (int i = lane; i < deg; i += 32) {
        int p = o0 + i;
        float a = g_eattr[p];
        int s = g_srcs[p];
        float4 ss = ((const float4*)g_ssrc1)[s];
        float4 al;
        al.x = ss.x + sd.x + a * ep.x;
        al.y = ss.y + sd.y + a * ep.y;
        al.z = ss.z + sd.z + a * ep.z;
        al.w = ss.w + sd.w + a * ep.w;
        al.x = al.x > 0.f ? al.x : 0.2f * al.x;
        al.y = al.y > 0.f ? al.y : 0.2f * al.y;
        al.z = al.z > 0.f ? al.z : 0.2f * al.z;
        al.w = al.w > 0.f ? al.w : 0.2f * al.w;
        g_alpha1[p] = al;
        mx.x = fmaxf(mx.x, al.x); mx.y = fmaxf(mx.y, al.y);
        mx.z = fmaxf(mx.z, al.z); mx.w = fmaxf(mx.w, al.w);
    }
#pragma unroll
    for (int off = 16; off; off >>= 1) {
        mx.x = fmaxf(mx.x, __shfl_xor_sync(0xffffffffu, mx.x, off));
        mx.y = fmaxf(mx.y, __shfl_xor_sync(0xffffffffu, mx.y, off));
        mx.z = fmaxf(mx.z, __shfl_xor_sync(0xffffffffu, mx.z, off));
        mx.w = fmaxf(mx.w, __shfl_xor_sync(0xffffffffu, mx.w, off));
    }
    __syncwarp();

    // pass B: exp + sum
    float4 se = make_float4(0.f, 0.f, 0.f, 0.f);
    for (int i = lane; i < deg; i += 32) {
        int p = o0 + i;
        float4 al = g_alpha1[p];
        al.x = __expf(al.x - mx.x); al.y = __expf(al.y - mx.y);
        al.z = __expf(al.z - mx.z); al.w = __expf(al.w - mx.w);
        g_alpha1[p] = al;
        se.x += al.x; se.y += al.y; se.z += al.z; se.w += al.w;
    }
#pragma unroll
    for (int off = 16; off; off >>= 1) {
        se.x += __shfl_xor_sync(0xffffffffu, se.x, off);
        se.y += __shfl_xor_sync(0xffffffffu, se.y, off);
        se.z += __shfl_xor_sync(0xffffffffu, se.z, off);
        se.w += __shfl_xor_sync(0xffffffffu, se.w, off);
    }
    float4 wv;
    wv.x = 1.f / (se.x + 1e-16f); wv.y = 1.f / (se.y + 1e-16f);
    wv.z = 1.f / (se.z + 1e-16f); wv.w = 1.f / (se.w + 1e-16f);
    __syncwarp();

    // pass C: coalesced gather; lane covers cols [lane*8, lane*8+8); unroll x2
    int h = lane >> 3;
    float wsel = (h == 0) ? wv.x : (h == 1) ? wv.y : (h == 2) ? wv.z : wv.w;
    float4 acc0 = make_float4(0.f, 0.f, 0.f, 0.f);
    float4 acc1 = make_float4(0.f, 0.f, 0.f, 0.f);
    int i = 0;
    for (; i + 2 <= deg; i += 2) {
        int p0 = o0 + i, p1 = o0 + i + 1;
        float4 a0 = g_alpha1[p0];
        float4 a1 = g_alpha1[p1];
        int s0 = g_srcs[p0];
        int s1 = g_srcs[p1];
        float w0 = ((h == 0) ? a0.x : (h == 1) ? a0.y : (h == 2) ? a0.z : a0.w) * wsel;
        float w1 = ((h == 0) ? a1.x : (h == 1) ? a1.y : (h == 2) ? a1.z : a1.w) * wsel;
        const float4* r0 = (const float4*)g_h1 + s0 * 64;
        const float4* r1 = (const float4*)g_h1 + s1 * 64;
        float4 v00 = r0[lane * 2], v01 = r0[lane * 2 + 1];
        float4 v10 = r1[lane * 2], v11 = r1[lane * 2 + 1];
        acc0.x += w0 * v00.x; acc0.y += w0 * v00.y; acc0.z += w0 * v00.z; acc0.w += w0 * v00.w;
        acc1.x += w0 * v01.x; acc1.y += w0 * v01.y; acc1.z += w0 * v01.z; acc1.w += w0 * v01.w;
        acc0.x += w1 * v10.x; acc0.y += w1 * v10.y; acc0.z += w1 * v10.z; acc0.w += w1 * v10.w;
        acc1.x += w1 * v11.x; acc1.y += w1 * v11.y; acc1.z += w1 * v11.z; acc1.w += w1 * v11.w;
    }
    if (i < deg) {
        int p = o0 + i;
        float4 a0 = g_alpha1[p];
        int s = g_srcs[p];
        float w0 = ((h == 0) ? a0.x : (h == 1) ? a0.y : (h == 2) ? a0.z : a0.w) * wsel;
        const float4* row = (const float4*)g_h1 + s * 64;
        float4 v0 = row[lane * 2], v1 = row[lane * 2 + 1];
        acc0.x += w0 * v0.x; acc0.y += w0 * v0.y; acc0.z += w0 * v0.z; acc0.w += w0 * v0.w;
        acc1.x += w0 * v1.x; acc1.y += w0 * v1.y; acc1.z += w0 * v1.z; acc1.w += w0 * v1.w;
    }
    float4 bb0 = ((const float4*)b1)[lane * 2], bb1 = ((const float4*)b1)[lane * 2 + 1];
    acc0.x += bb0.x; acc0.y += bb0.y; acc0.z += bb0.z; acc0.w += bb0.w;
    acc1.x += bb1.x; acc1.y += bb1.y; acc1.z += bb1.z; acc1.w += bb1.w;
    acc0.x = acc0.x > 0.f ? acc0.x : (__expf(acc0.x) - 1.f);
    acc0.y = acc0.y > 0.f ? acc0.y : (__expf(acc0.y) - 1.f);
    acc0.z = acc0.z > 0.f ? acc0.z : (__expf(acc0.z) - 1.f);
    acc0.w = acc0.w > 0.f ? acc0.w : (__expf(acc0.w) - 1.f);
    acc1.x = acc1.x > 0.f ? acc1.x : (__expf(acc1.x) - 1.f);
    acc1.y = acc1.y > 0.f ? acc1.y : (__expf(acc1.y) - 1.f);
    acc1.z = acc1.z > 0.f ? acc1.z : (__expf(acc1.z) - 1.f);
    acc1.w = acc1.w > 0.f ? acc1.w : (__expf(acc1.w) - 1.f);
    float4* orow = (float4*)g_out1 + n * 64;
    orow[lane * 2] = acc0;
    orow[lane * 2 + 1] = acc1;
}

// warp per dst node, layer2 (1 head, 64 cols) -> final output + bias2
__global__ void __launch_bounds__(256) k_agg2(const float* __restrict__ b2,
                                              float* __restrict__ dout) {
    int n = (blockIdx.x * blockDim.x + threadIdx.x) >> 5;
    int lane = threadIdx.x & 31;
    if (n >= NN) return;
    int o0 = g_off[n], deg = g_off[n + 1] - o0;
    float ep = g_eproj[4];
    float sdn = g_sdst2[n];

    float mx = -1e30f;
    for (int i = lane; i < deg; i += 32) {
        int p = o0 + i;
        float a = g_eattr[p];
        int s = g_srcs[p];
        float al = g_ssrc2[s] + sdn + a * ep;
        al = al > 0.f ? al : 0.2f * al;
        g_alpha2[p] = al;
        mx = fmaxf(mx, al);
    }
#pragma unroll
    for (int off = 16; off; off >>= 1) mx = fmaxf(mx, __shfl_xor_sync(0xffffffffu, mx, off));
    __syncwarp();

    float se = 0.f;
    for (int i = lane; i < deg; i += 32) {
        int p = o0 + i;
        float v = __expf(g_alpha2[p] - mx);
        g_alpha2[p] = v;
        se += v;
    }
#pragma unroll
    for (int off = 16; off; off >>= 1) se += __shfl_xor_sync(0xffffffffu, se, off);
    float w = 1.f / (se + 1e-16f);
    __syncwarp();

    float2 acc = make_float2(0.f, 0.f);
    int i = 0;
    for (; i + 2 <= deg; i += 2) {
        int p0 = o0 + i, p1 = o0 + i + 1;
        float w0 = g_alpha2[p0] * w;
        float w1 = g_alpha2[p1] * w;
        int s0 = g_srcs[p0];
        int s1 = g_srcs[p1];
        float2 v0 = ((const float2*)(g_h2 + s0 * 64))[lane];
        float2 v1 = ((const float2*)(g_h2 + s1 * 64))[lane];
        acc.x += w0 * v0.x + w1 * v1.x;
        acc.y += w0 * v0.y + w1 * v1.y;
    }
    if (i < deg) {
        int p = o0 + i;
        float w0 = g_alpha2[p] * w;
        int s = g_srcs[p];
        float2 v = ((const float2*)(g_h2 + s * 64))[lane];
        acc.x += w0 * v.x;
        acc.y += w0 * v.y;
    }
    float2 bb = ((const float2*)b2)[lane];
    ((float2*)(dout + n * 64))[lane] = make_float2(acc.x + bb.x, acc.y + bb.y);
}

// ---------------- launch ----------------
extern "C" void kernel_launch(void* const* d_in, const int* in_sizes, int n_in,
                              void* d_out, int out_size) {
    const float* x   = (const float*)d_in[0];
    const int*   ei  = (const int*)d_in[1];
    const float* ea  = (const float*)d_in[2];
    const float* W1  = (const float*)d_in[3];
    const float* We1 = (const float*)d_in[4];
    const float* as1 = (const float*)d_in[5];
    const float* ad1 = (const float*)d_in[6];
    const float* ae1 = (const float*)d_in[7];
    const float* b1  = (const float*)d_in[8];
    const float* W2  = (const float*)d_in[9];
    const float* We2 = (const float*)d_in[10];
    const float* as2 = (const float*)d_in[11];
    const float* ad2 = (const float*)d_in[12];
    const float* ae2 = (const float*)d_in[13];
    const float* b2  = (const float*)d_in[14];
    float* dout = (float*)d_out;

    const int* src = ei;
    const int* dst = ei + NE;

    const int WPB = 8;                         // warps (nodes) per 256-thread block
    const int NB  = (NN + WPB - 1) / WPB;      // 6250

    k_init<<<(NN + 255) / 256, 256>>>(We1, ae1, We2, ae2);
    k_hist<<<(NE + 255) / 256, 256>>>(dst, ea);
    k_scan<<<1, 1024>>>();
    k_fill<<<(ET + 255) / 256, 256>>>(src, dst, ea);

    k_gemm1<<<(NN + 31) / 32, 256>>>(x, W1, as1, ad1);
    k_agg1<<<NB, 256>>>(b1);

    k_gemm2<<<(NN + 47) / 48, 256>>>(W2, as2, ad2);
    k_agg2<<<NB, 256>>>(b2, dout);
}

// round 8
// speedup vs baseline: 1.1206x; 1.0422x over previous
#include <cuda_runtime.h>
#include <math.h>

// Problem constants
#define NN 50000          // nodes
#define NE 500000         // original edges
#define ET (NE + NN)      // edges + self loops = 550000
#define D1 256            // layer1 out (4 heads x 64)
#define C2 64
#define IND 128

// ---------------- device scratch (static, no allocation) ----------------
__device__ float  g_h1[NN * D1];        // layer1 projected features
__device__ float  g_out1[NN * D1];      // layer1 aggregated+elu output
__device__ float  g_h2[NN * C2];        // layer2 projected features
__device__ float  g_ssrc1[NN * 4];
__device__ float  g_sdst1[NN * 4];
__device__ float  g_ssrc2[NN];
__device__ float  g_sdst2[NN];
__device__ float4 g_alpha1[ET];         // pre-exp attention logits (leaky-relu'd)
__device__ float  g_alpha2[ET];
__device__ float  g_loop[NN];
__device__ __align__(16) float g_eproj[8];   // [0..3]=layer1 heads, [4]=layer2
// CSR
__device__ int    g_deg[NN];
__device__ int    g_off[NN + 1];
__device__ int    g_cur[NN];
__device__ int    g_srcs[ET];
__device__ float  g_eattr[ET];          // edge attr (loop attr for self loops)
__device__ float  g_sum[NN];

// ---------------- init: deg=1 (self loop), sum=0, eproj scalars ----------------
__global__ void k_init(const float* __restrict__ We1, const float* __restrict__ ae1,
                       const float* __restrict__ We2, const float* __restrict__ ae2) {
    int i = blockIdx.x * blockDim.x + threadIdx.x;
    if (i < NN) { g_deg[i] = 1; g_sum[i] = 0.f; }
    if (blockIdx.x == 0) {
        __shared__ float sm[256];
        int t = threadIdx.x;
        sm[t] = We1[t] * ae1[t];
        __syncthreads();
        if (t < 4) {
            float s = 0.f;
            for (int j = 0; j < 64; j++) s += sm[t * 64 + j];
            g_eproj[t] = s;
        }
        __syncthreads();
        if (t < 64) sm[t] = We2[t] * ae2[t];
        __syncthreads();
        if (t == 0) {
            float s = 0.f;
            for (int j = 0; j < 64; j++) s += sm[j];
            g_eproj[4] = s;
        }
    }
}

__global__ void k_hist(const int* __restrict__ dst, const float* __restrict__ ea) {
    int e = blockIdx.x * blockDim.x + threadIdx.x;
    if (e >= NE) return;
    int d = dst[e];
    atomicAdd(&g_deg[d], 1);
    atomicAdd(&g_sum[d], ea[e]);
}

// single block 1024 threads: exclusive scan deg->off/cur, and loop attr
__global__ void k_scan() {
    __shared__ int part[1024];
    int t = threadIdx.x;
    const int CH = 49;                        // 1024*49 = 50176 >= NN
    int base = t * CH;
    int s = 0;
    for (int i = 0; i < CH; i++) {
        int idx = base + i;
        if (idx < NN) s += g_deg[idx];
    }
    part[t] = s;
    __syncthreads();
    for (int off = 1; off < 1024; off <<= 1) {
        int v = (t >= off) ? part[t - off] : 0;
        __syncthreads();
        part[t] += v;
        __syncthreads();
    }
    int run = part[t] - s;                    // exclusive prefix
    for (int i = 0; i < CH; i++) {
        int idx = base + i;
        if (idx < NN) {
            int d = g_deg[idx];
            g_off[idx] = run; g_cur[idx] = run;
            g_loop[idx] = g_sum[idx] / fmaxf((float)(d - 1), 1.f);
            run += d;
        }
    }
    if (t == 1023) g_off[NN] = part[1023];
}

__global__ void k_fill(const int* __restrict__ src, const int* __restrict__ dst,
                       const float* __restrict__ ea) {
    int e = blockIdx.x * blockDim.x + threadIdx.x;
    if (e >= ET) return;
    int s, d; float a;
    if (e < NE) { s = src[e]; d = dst[e]; a = ea[e]; }
    else { s = e - NE; d = s; a = g_loop[s]; }
    int pos = atomicAdd(&g_cur[d], 1);
    g_srcs[pos] = s;
    g_eattr[pos] = a;
}

// ---------------- GEMMs (plain FFMA, scores fused into epilogue) ----------------

// GEMM1: h1 = x @ W1. Block: 32 nodes x 256 cols; thread: 8 nodes x 4 cols.
__global__ void __launch_bounds__(256) k_gemm1(const float* __restrict__ x,
                                               const float* __restrict__ W1,
                                               const float* __restrict__ as1,
                                               const float* __restrict__ ad1) {
    __shared__ __align__(16) float xs[32 * IND];     // 16KB
    int t = threadIdx.x;
    int tx = t & 63, ty = t >> 6;
    int nodeBase = blockIdx.x * 32;
    const float4* xg = (const float4*)x;
    float4* xs4 = (float4*)xs;
#pragma unroll
    for (int i = 0; i < 4; i++) {
        int idx = i * 256 + t;
        int gidx = nodeBase * 32 + idx;
        xs4[idx] = (gidx < NN * 32) ? xg[gidx] : make_float4(0.f, 0.f, 0.f, 0.f);
    }
    __syncthreads();
    float4 acc[8];
#pragma unroll
    for (int i = 0; i < 8; i++) acc[i] = make_float4(0.f, 0.f, 0.f, 0.f);
    const float4* __restrict__ W4 = (const float4*)W1;
    const float* xrow = xs + ty * 8 * IND;
#pragma unroll 4
    for (int k = 0; k < IND; k++) {
        float4 w = W4[k * 64 + tx];
#pragma unroll
        for (int i = 0; i < 8; i++) {
            float xv = xrow[i * IND + k];
            acc[i].x += xv * w.x; acc[i].y += xv * w.y;
            acc[i].z += xv * w.z; acc[i].w += xv * w.w;
        }
    }
#pragma unroll
    for (int i = 0; i < 8; i++) {
        int node = nodeBase + ty * 8 + i;
        if (node < NN) ((float4*)g_h1)[node * 64 + tx] = acc[i];
    }
    // fused score epilogue: head h = tx>>4 owns float4 cols [16h,16h+16)
    float4 av = ((const float4*)as1)[tx];
    float4 dv = ((const float4*)ad1)[tx];
    float ps[8], pd[8];
#pragma unroll
    for (int i = 0; i < 8; i++) {
        ps[i] = acc[i].x * av.x + acc[i].y * av.y + acc[i].z * av.z + acc[i].w * av.w;
        pd[i] = acc[i].x * dv.x + acc[i].y * dv.y + acc[i].z * dv.z + acc[i].w * dv.w;
    }
#pragma unroll
    for (int off = 8; off; off >>= 1) {
#pragma unroll
        for (int i = 0; i < 8; i++) {
            ps[i] += __shfl_xor_sync(0xffffffffu, ps[i], off);
            pd[i] += __shfl_xor_sync(0xffffffffu, pd[i], off);
        }
    }
    if ((tx & 15) == 0) {
        int h = tx >> 4;
#pragma unroll
        for (int i = 0; i < 8; i++) {
            int node = nodeBase + ty * 8 + i;
            if (node < NN) {
                g_ssrc1[node * 4 + h] = ps[i];
                g_sdst1[node * 4 + h] = pd[i];
            }
        }
    }
}

// GEMM2: h2 = out1 @ W2. Block: 48 nodes x 64 cols; thread: 3 nodes x 4 cols.
__global__ void __launch_bounds__(256) k_gemm2(const float* __restrict__ W2,
                                               const float* __restrict__ as2,
                                               const float* __restrict__ ad2) {
    __shared__ __align__(16) float xs[48 * D1];      // 48KB
    int t = threadIdx.x;
    int tx = t & 15, ty = t >> 4;
    int nodeBase = blockIdx.x * 48;
    const float4* xg = (const float4*)g_out1;
    float4* xs4 = (float4*)xs;
#pragma unroll
    for (int i = 0; i < 12; i++) {
        int idx = i * 256 + t;
        int gidx = nodeBase * 64 + idx;
        xs4[idx] = (gidx < NN * 64) ? xg[gidx] : make_float4(0.f, 0.f, 0.f, 0.f);
    }
    __syncthreads();
    float4 acc[3];
#pragma unroll
    for (int i = 0; i < 3; i++) acc[i] = make_float4(0.f, 0.f, 0.f, 0.f);
    const float4* __restrict__ W4 = (const float4*)W2;
    const float* xrow = xs + ty * 3 * D1;
#pragma unroll 4
    for (int k = 0; k < D1; k++) {
        float4 w = W4[k * 16 + tx];
#pragma unroll
        for (int i = 0; i < 3; i++) {
            float xv = xrow[i * D1 + k];
            acc[i].x += xv * w.x; acc[i].y += xv * w.y;
            acc[i].z += xv * w.z; acc[i].w += xv * w.w;
        }
    }
#pragma unroll
    for (int i = 0; i < 3; i++) {
        int node = nodeBase + ty * 3 + i;
        if (node < NN) ((float4*)g_h2)[node * 16 + tx] = acc[i];
    }
    float4 av = ((const float4*)as2)[tx];
    float4 dv = ((const float4*)ad2)[tx];
    float ps[3], pd[3];
#pragma unroll
    for (int i = 0; i < 3; i++) {
        ps[i] = acc[i].x * av.x + acc[i].y * av.y + acc[i].z * av.z + acc[i].w * av.w;
        pd[i] = acc[i].x * dv.x + acc[i].y * dv.y + acc[i].z * dv.z + acc[i].w * dv.w;
    }
#pragma unroll
    for (int off = 8; off; off >>= 1) {
#pragma unroll
        for (int i = 0; i < 3; i++) {
            ps[i] += __shfl_xor_sync(0xffffffffu, ps[i], off);
            pd[i] += __shfl_xor_sync(0xffffffffu, pd[i], off);
        }
    }
    if (tx == 0) {
#pragma unroll
        for (int i = 0; i < 3; i++) {
            int node = nodeBase + ty * 3 + i;
            if (node < NN) { g_ssrc2[node] = ps[i]; g_sdst2[node] = pd[i]; }
        }
    }
}

// ---------------- fused softmax + aggregation (2-pass, deferred norm) ----------

// warp per dst node, layer1 (4 heads, 256 feature cols)
__global__ void __launch_bounds__(256) k_agg1(const float* __restrict__ b1) {
    int n = (blockIdx.x * blockDim.x + threadIdx.x) >> 5;
    int lane = threadIdx.x & 31;
    if (n >= NN) return;
    int o0 = g_off[n], deg = g_off[n + 1] - o0;
    float4 ep = *((const float4*)g_eproj);
    float4 sd = ((const float4*)g_sdst1)[n];

    // pass A: alpha (leaky relu), per-head max; store PRE-EXP logits
    float4 mx = make_float4(-1e30f, -1e30f, -1e30f, -1e30f);
    for (int i = lane; i < deg; i += 32) {
        int p = o0 + i;
        float a = g_eattr[p];
        int s = g_srcs[p];
        float4 ss = ((const float4*)g_ssrc1)[s];
        float4 al;
        al.x = ss.x + sd.x + a * ep.x;
        al.y = ss.y + sd.y + a * ep.y;
        al.z = ss.z + sd.z + a * ep.z;
        al.w = ss.w + sd.w + a * ep.w;
        al.x = al.x > 0.f ? al.x : 0.2f * al.x;
        al.y = al.y > 0.f ? al.y : 0.2f * al.y;
        al.z = al.z > 0.f ? al.z : 0.2f * al.z;
        al.w = al.w > 0.f ? al.w : 0.2f * al.w;
        g_alpha1[p] = al;
        mx.x = fmaxf(mx.x, al.x); mx.y = fmaxf(mx.y, al.y);
        mx.z = fmaxf(mx.z, al.z); mx.w = fmaxf(mx.w, al.w);
    }
#pragma unroll
    for (int off = 16; off; off >>= 1) {
        mx.x = fmaxf(mx.x, __shfl_xor_sync(0xffffffffu, mx.x, off));
        mx.y = fmaxf(mx.y, __shfl_xor_sync(0xffffffffu, mx.y, off));
        mx.z = fmaxf(mx.z, __shfl_xor_sync(0xffffffffu, mx.z, off));
        mx.w = fmaxf(mx.w, __shfl_xor_sync(0xffffffffu, mx.w, off));
    }
    __syncwarp();

    // pass B: gather with exp-on-the-fly; every lane walks all edges, so the
    // per-lane side-sum se equals the full per-head denominator. Normalize at end.
    int h = lane >> 3;
    float mxh = (h == 0) ? mx.x : (h == 1) ? mx.y : (h == 2) ? mx.z : mx.w;
    float4 acc0 = make_float4(0.f, 0.f, 0.f, 0.f);
    float4 acc1 = make_float4(0.f, 0.f, 0.f, 0.f);
    float se = 0.f;
    int i = 0;
    for (; i + 2 <= deg; i += 2) {
        int p0 = o0 + i, p1 = o0 + i + 1;
        float4 a0 = g_alpha1[p0];
        float4 a1 = g_alpha1[p1];
        int s0 = g_srcs[p0];
        int s1 = g_srcs[p1];
        float l0 = (h == 0) ? a0.x : (h == 1) ? a0.y : (h == 2) ? a0.z : a0.w;
        float l1 = (h == 0) ? a1.x : (h == 1) ? a1.y : (h == 2) ? a1.z : a1.w;
        float w0 = __expf(l0 - mxh);
        float w1 = __expf(l1 - mxh);
        se += w0 + w1;
        const float4* r0 = (const float4*)g_h1 + s0 * 64;
        const float4* r1 = (const float4*)g_h1 + s1 * 64;
        float4 v00 = r0[lane * 2], v01 = r0[lane * 2 + 1];
        float4 v10 = r1[lane * 2], v11 = r1[lane * 2 + 1];
        acc0.x += w0 * v00.x; acc0.y += w0 * v00.y; acc0.z += w0 * v00.z; acc0.w += w0 * v00.w;
        acc1.x += w0 * v01.x; acc1.y += w0 * v01.y; acc1.z += w0 * v01.z; acc1.w += w0 * v01.w;
        acc0.x += w1 * v10.x; acc0.y += w1 * v10.y; acc0.z += w1 * v10.z; acc0.w += w1 * v10.w;
        acc1.x += w1 * v11.x; acc1.y += w1 * v11.y; acc1.z += w1 * v11.z; acc1.w += w1 * v11.w;
    }
    if (i < deg) {
        int p = o0 + i;
        float4 a0 = g_alpha1[p];
        int s = g_srcs[p];
        float l0 = (h == 0) ? a0.x : (h == 1) ? a0.y : (h == 2) ? a0.z : a0.w;
        float w0 = __expf(l0 - mxh);
        se += w0;
        const float4* row = (const float4*)g_h1 + s * 64;
        float4 v0 = row[lane * 2], v1 = row[lane * 2 + 1];
        acc0.x += w0 * v0.x; acc0.y += w0 * v0.y; acc0.z += w0 * v0.z; acc0.w += w0 * v0.w;
        acc1.x += w0 * v1.x; acc1.y += w0 * v1.y; acc1.z += w0 * v1.z; acc1.w += w0 * v1.w;
    }
    float inv = 1.f / (se + 1e-16f);
    acc0.x *= inv; acc0.y *= inv; acc0.z *= inv; acc0.w *= inv;
    acc1.x *= inv; acc1.y *= inv; acc1.z *= inv; acc1.w *= inv;
    float4 bb0 = ((const float4*)b1)[lane * 2], bb1 = ((const float4*)b1)[lane * 2 + 1];
    acc0.x += bb0.x; acc0.y += bb0.y; acc0.z += bb0.z; acc0.w += bb0.w;
    acc1.x += bb1.x; acc1.y += bb1.y; acc1.z += bb1.z; acc1.w += bb1.w;
    acc0.x = acc0.x > 0.f ? acc0.x : (__expf(acc0.x) - 1.f);
    acc0.y = acc0.y > 0.f ? acc0.y : (__expf(acc0.y) - 1.f);
    acc0.z = acc0.z > 0.f ? acc0.z : (__expf(acc0.z) - 1.f);
    acc0.w = acc0.w > 0.f ? acc0.w : (__expf(acc0.w) - 1.f);
    acc1.x = acc1.x > 0.f ? acc1.x : (__expf(acc1.x) - 1.f);
    acc1.y = acc1.y > 0.f ? acc1.y : (__expf(acc1.y) - 1.f);
    acc1.z = acc1.z > 0.f ? acc1.z : (__expf(acc1.z) - 1.f);
    acc1.w = acc1.w > 0.f ? acc1.w : (__expf(acc1.w) - 1.f);
    float4* orow = (float4*)g_out1 + n * 64;
    orow[lane * 2] = acc0;
    orow[lane * 2 + 1] = acc1;
}

// warp per dst node, layer2 (1 head, 64 cols) -> final output + bias2
__global__ void __launch_bounds__(256) k_agg2(const float* __restrict__ b2,
                                              float* __restrict__ dout) {
    int n = (blockIdx.x * blockDim.x + threadIdx.x) >> 5;
    int lane = threadIdx.x & 31;
    if (n >= NN) return;
    int o0 = g_off[n], deg = g_off[n + 1] - o0;
    float ep = g_eproj[4];
    float sdn = g_sdst2[n];

    float mx = -1e30f;
    for (int i = lane; i < deg; i += 32) {
        int p = o0 + i;
        float a = g_eattr[p];
        int s = g_srcs[p];
        float al = g_ssrc2[s] + sdn + a * ep;
        al = al > 0.f ? al : 0.2f * al;
        g_alpha2[p] = al;
        mx = fmaxf(mx, al);
    }
#pragma unroll
    for (int off = 16; off; off >>= 1) mx = fmaxf(mx, __shfl_xor_sync(0xffffffffu, mx, off));
    __syncwarp();

    float2 acc = make_float2(0.f, 0.f);
    float se = 0.f;
    int i = 0;
    for (; i + 2 <= deg; i += 2) {
        int p0 = o0 + i, p1 = o0 + i + 1;
        float w0 = __expf(g_alpha2[p0] - mx);
        float w1 = __expf(g_alpha2[p1] - mx);
        int s0 = g_srcs[p0];
        int s1 = g_srcs[p1];
        se += w0 + w1;
        float2 v0 = ((const float2*)(g_h2 + s0 * 64))[lane];
        float2 v1 = ((const float2*)(g_h2 + s1 * 64))[lane];
        acc.x += w0 * v0.x + w1 * v1.x;
        acc.y += w0 * v0.y + w1 * v1.y;
    }
    if (i < deg) {
        int p = o0 + i;
        float w0 = __expf(g_alpha2[p] - mx);
        int s = g_srcs[p];
        se += w0;
        float2 v = ((const float2*)(g_h2 + s * 64))[lane];
        acc.x += w0 * v.x;
        acc.y += w0 * v.y;
    }
    float inv = 1.f / (se + 1e-16f);
    float2 bb = ((const float2*)b2)[lane];
    ((float2*)(dout + n * 64))[lane] = make_float2(acc.x * inv + bb.x, acc.y * inv + bb.y);
}

// ---------------- launch ----------------
extern "C" void kernel_launch(void* const* d_in, const int* in_sizes, int n_in,
                              void* d_out, int out_size) {
    const float* x   = (const float*)d_in[0];
    const int*   ei  = (const int*)d_in[1];
    const float* ea  = (const float*)d_in[2];
    const float* W1  = (const float*)d_in[3];
    const float* We1 = (const float*)d_in[4];
    const float* as1 = (const float*)d_in[5];
    const float* ad1 = (const float*)d_in[6];
    const float* ae1 = (const float*)d_in[7];
    const float* b1  = (const float*)d_in[8];
    const float* W2  = (const float*)d_in[9];
    const float* We2 = (const float*)d_in[10];
    const float* as2 = (const float*)d_in[11];
    const float* ad2 = (const float*)d_in[12];
    const float* ae2 = (const float*)d_in[13];
    const float* b2  = (const float*)d_in[14];
    float* dout = (float*)d_out;

    const int* src = ei;
    const int* dst = ei + NE;

    const int WPB = 8;                         // warps (nodes) per 256-thread block
    const int NB  = (NN + WPB - 1) / WPB;      // 6250

    // Try to fork k_gemm1 (independent of the CSR chain) onto a second stream.
    cudaStream_t s2 = 0;
    cudaEvent_t evFork = 0, evJoin = 0;
    bool fork_ok =
        (cudaStreamCreateWithFlags(&s2, cudaStreamNonBlocking) == cudaSuccess);
    if (fork_ok) fork_ok = (cudaEventCreateWithFlags(&evFork, cudaEventDisableTiming) == cudaSuccess);
    if (fork_ok) fork_ok = (cudaEventCreateWithFlags(&evJoin, cudaEventDisableTiming) == cudaSuccess);

    if (fork_ok) {
        fork_ok = (cudaEventRecord(evFork, 0) == cudaSuccess) &&
                  (cudaStreamWaitEvent(s2, evFork, 0) == cudaSuccess);
    }

    if (fork_ok) {
        // branch 1 (s2): layer1 GEMM
        k_gemm1<<<(NN + 31) / 32, 256, 0, s2>>>(x, W1, as1, ad1);
        cudaEventRecord(evJoin, s2);
        // branch 2 (origin stream): CSR build
        k_init<<<(NN + 255) / 256, 256>>>(We1, ae1, We2, ae2);
        k_hist<<<(NE + 255) / 256, 256>>>(dst, ea);
        k_scan<<<1, 1024>>>();
        k_fill<<<(ET + 255) / 256, 256>>>(src, dst, ea);
        cudaStreamWaitEvent(0, evJoin, 0);     // join
    } else {
        // serial fallback
        k_init<<<(NN + 255) / 256, 256>>>(We1, ae1, We2, ae2);
        k_hist<<<(NE + 255) / 256, 256>>>(dst, ea);
        k_scan<<<1, 1024>>>();
        k_fill<<<(ET + 255) / 256, 256>>>(src, dst, ea);
        k_gemm1<<<(NN + 31) / 32, 256>>>(x, W1, as1, ad1);
    }

    k_agg1<<<NB, 256>>>(b1);
    k_gemm2<<<(NN + 47) / 48, 256>>>(W2, as2, ad2);
    k_agg2<<<NB, 256>>>(b2, dout);

    if (evFork) cudaEventDestroy(evFork);
    if (evJoin) cudaEventDestroy(evJoin);
    if (s2) cudaStreamDestroy(s2);
}

// round 9
// speedup vs baseline: 1.6276x; 1.4525x over previous
#include <cuda_runtime.h>
#include <math.h>

// Problem constants
#define NN 50000          // nodes
#define NE 500000         // original edges
#define ET (NE + NN)      // edges + self loops = 550000
#define D1 256            // layer1 out (4 heads x 64)
#define C2 64
#define IND 128
#define SB  ((NN + 255) / 256)   // scan blocks = 196

// ---------------- device scratch (static, no allocation) ----------------
__device__ float  g_h1[NN * D1];        // layer1 projected features
__device__ float  g_out1[NN * D1];      // layer1 aggregated+elu output
__device__ float  g_h2[NN * C2];        // layer2 projected features
__device__ float  g_ssrc1[NN * 4];
__device__ float  g_sdst1[NN * 4];
__device__ float  g_ssrc2[NN];
__device__ float  g_sdst2[NN];
__device__ float4 g_alpha1[ET];         // pre-exp attention logits (leaky-relu'd)
__device__ float  g_alpha2[ET];
__device__ float  g_loop[NN];
__device__ __align__(16) float g_eproj[8];   // [0..3]=layer1 heads, [4]=layer2
// CSR
__device__ int    g_deg[NN];
__device__ int    g_off[NN + 1];
__device__ int    g_cur[NN];
__device__ int    g_srcs[ET];
__device__ float  g_eattr[ET];          // edge attr (loop attr for self loops)
__device__ float  g_sum[NN];
__device__ int    g_bsum[SB];
__device__ int    g_boff[SB];

// ---------------- init: deg=1 (self loop), sum=0, eproj scalars ----------------
__global__ void k_init(const float* __restrict__ We1, const float* __restrict__ ae1,
                       const float* __restrict__ We2, const float* __restrict__ ae2) {
    int i = blockIdx.x * blockDim.x + threadIdx.x;
    if (i < NN) { g_deg[i] = 1; g_sum[i] = 0.f; }
    if (blockIdx.x == 0) {
        __shared__ float sm[256];
        int t = threadIdx.x;
        sm[t] = We1[t] * ae1[t];
        __syncthreads();
        if (t < 4) {
            float s = 0.f;
            for (int j = 0; j < 64; j++) s += sm[t * 64 + j];
            g_eproj[t] = s;
        }
        __syncthreads();
        if (t < 64) sm[t] = We2[t] * ae2[t];
        __syncthreads();
        if (t == 0) {
            float s = 0.f;
            for (int j = 0; j < 64; j++) s += sm[j];
            g_eproj[4] = s;
        }
    }
}

__global__ void k_hist(const int* __restrict__ dst, const float* __restrict__ ea) {
    int e = blockIdx.x * blockDim.x + threadIdx.x;
    if (e >= NE) return;
    int d = dst[e];
    atomicAdd(&g_deg[d], 1);
    atomicAdd(&g_sum[d], ea[e]);
}

// ---------------- 3-phase decoupled scan (coalesced) ----------------

// phase 1: per-block sums of g_deg
__global__ void k_scan1() {
    int b = blockIdx.x, t = threadIdx.x;
    int i = b * 256 + t;
    int v = (i < NN) ? g_deg[i] : 0;
#pragma unroll
    for (int off = 16; off; off >>= 1) v += __shfl_xor_sync(0xffffffffu, v, off);
    __shared__ int ws[8];
    if ((t & 31) == 0) ws[t >> 5] = v;
    __syncthreads();
    if (t == 0) {
        int s = 0;
#pragma unroll
        for (int j = 0; j < 8; j++) s += ws[j];
        g_bsum[b] = s;
    }
}

// phase 2: single block exclusive scan of the SB block sums
__global__ void k_scan2() {
    __shared__ int sm[256];
    int t = threadIdx.x;
    int v = (t < SB) ? g_bsum[t] : 0;
    sm[t] = v;
    __syncthreads();
    for (int off = 1; off < 256; off <<= 1) {
        int y = (t >= off) ? sm[t - off] : 0;
        __syncthreads();
        sm[t] += y;
        __syncthreads();
    }
    if (t < SB) g_boff[t] = sm[t] - v;
    if (t == 0) g_off[NN] = ET;      // total degree is always NE + NN
}

// phase 3: per-block exclusive scan + global offset; write off/cur/loop
__global__ void k_scan3() {
    int b = blockIdx.x, t = threadIdx.x;
    int lane = t & 31, w = t >> 5;
    int i = b * 256 + t;
    int v = (i < NN) ? g_deg[i] : 0;
    // inclusive warp scan
    int x = v;
#pragma unroll
    for (int off = 1; off < 32; off <<= 1) {
        int y = __shfl_up_sync(0xffffffffu, x, off);
        if (lane >= off) x += y;
    }
    __shared__ int ws[8];
    if (lane == 31) ws[w] = x;
    __syncthreads();
    if (t == 0) {
        int run = 0;
#pragma unroll
        for (int j = 0; j < 8; j++) { int tmp = ws[j]; ws[j] = run; run += tmp; }
    }
    __syncthreads();
    int excl = (x - v) + ws[w] + g_boff[b];
    if (i < NN) {
        g_off[i] = excl;
        g_cur[i] = excl;
        g_loop[i] = g_sum[i] / fmaxf((float)(v - 1), 1.f);
    }
}

__global__ void k_fill(const int* __restrict__ src, const int* __restrict__ dst,
                       const float* __restrict__ ea) {
    int e = blockIdx.x * blockDim.x + threadIdx.x;
    if (e >= ET) return;
    int s, d; float a;
    if (e < NE) { s = src[e]; d = dst[e]; a = ea[e]; }
    else { s = e - NE; d = s; a = g_loop[s]; }
    int pos = atomicAdd(&g_cur[d], 1);
    g_srcs[pos] = s;
    g_eattr[pos] = a;
}

// ---------------- GEMMs (plain FFMA, scores fused into epilogue) ----------------

// GEMM1: h1 = x @ W1. Block: 32 nodes x 256 cols; thread: 8 nodes x 4 cols.
__global__ void __launch_bounds__(256) k_gemm1(const float* __restrict__ x,
                                               const float* __restrict__ W1,
                                               const float* __restrict__ as1,
                                               const float* __restrict__ ad1) {
    __shared__ __align__(16) float xs[32 * IND];     // 16KB
    int t = threadIdx.x;
    int tx = t & 63, ty = t >> 6;
    int nodeBase = blockIdx.x * 32;
    const float4* xg = (const float4*)x;
    float4* xs4 = (float4*)xs;
#pragma unroll
    for (int i = 0; i < 4; i++) {
        int idx = i * 256 + t;
        int gidx = nodeBase * 32 + idx;
        xs4[idx] = (gidx < NN * 32) ? xg[gidx] : make_float4(0.f, 0.f, 0.f, 0.f);
    }
    __syncthreads();
    float4 acc[8];
#pragma unroll
    for (int i = 0; i < 8; i++) acc[i] = make_float4(0.f, 0.f, 0.f, 0.f);
    const float4* __restrict__ W4 = (const float4*)W1;
    const float* xrow = xs + ty * 8 * IND;
#pragma unroll 4
    for (int k = 0; k < IND; k++) {
        float4 w = W4[k * 64 + tx];
#pragma unroll
        for (int i = 0; i < 8; i++) {
            float xv = xrow[i * IND + k];
            acc[i].x += xv * w.x; acc[i].y += xv * w.y;
            acc[i].z += xv * w.z; acc[i].w += xv * w.w;
        }
    }
#pragma unroll
    for (int i = 0; i < 8; i++) {
        int node = nodeBase + ty * 8 + i;
        if (node < NN) ((float4*)g_h1)[node * 64 + tx] = acc[i];
    }
    // fused score epilogue: head h = tx>>4 owns float4 cols [16h,16h+16)
    float4 av = ((const float4*)as1)[tx];
    float4 dv = ((const float4*)ad1)[tx];
    float ps[8], pd[8];
#pragma unroll
    for (int i = 0; i < 8; i++) {
        ps[i] = acc[i].x * av.x + acc[i].y * av.y + acc[i].z * av.z + acc[i].w * av.w;
        pd[i] = acc[i].x * dv.x + acc[i].y * dv.y + acc[i].z * dv.z + acc[i].w * dv.w;
    }
#pragma unroll
    for (int off = 8; off; off >>= 1) {
#pragma unroll
        for (int i = 0; i < 8; i++) {
            ps[i] += __shfl_xor_sync(0xffffffffu, ps[i], off);
            pd[i] += __shfl_xor_sync(0xffffffffu, pd[i], off);
        }
    }
    if ((tx & 15) == 0) {
        int h = tx >> 4;
#pragma unroll
        for (int i = 0; i < 8; i++) {
            int node = nodeBase + ty * 8 + i;
            if (node < NN) {
                g_ssrc1[node * 4 + h] = ps[i];
                g_sdst1[node * 4 + h] = pd[i];
            }
        }
    }
}

// GEMM2: h2 = out1 @ W2. Block: 48 nodes x 64 cols; thread: 3 nodes x 4 cols.
__global__ void __launch_bounds__(256) k_gemm2(const float* __restrict__ W2,
                                               const float* __restrict__ as2,
                                               const float* __restrict__ ad2) {
    __shared__ __align__(16) float xs[48 * D1];      // 48KB
    int t = threadIdx.x;
    int tx = t & 15, ty = t >> 4;
    int nodeBase = blockIdx.x * 48;
    const float4* xg = (const float4*)g_out1;
    float4* xs4 = (float4*)xs;
#pragma unroll
    for (int i = 0; i < 12; i++) {
        int idx = i * 256 + t;
        int gidx = nodeBase * 64 + idx;
        xs4[idx] = (gidx < NN * 64) ? xg[gidx] : make_float4(0.f, 0.f, 0.f, 0.f);
    }
    __syncthreads();
    float4 acc[3];
#pragma unroll
    for (int i = 0; i < 3; i++) acc[i] = make_float4(0.f, 0.f, 0.f, 0.f);
    const float4* __restrict__ W4 = (const float4*)W2;
    const float* xrow = xs + ty * 3 * D1;
#pragma unroll 4
    for (int k = 0; k < D1; k++) {
        float4 w = W4[k * 16 + tx];
#pragma unroll
        for (int i = 0; i < 3; i++) {
            float xv = xrow[i * D1 + k];
            acc[i].x += xv * w.x; acc[i].y += xv * w.y;
            acc[i].z += xv * w.z; acc[i].w += xv * w.w;
        }
    }
#pragma unroll
    for (int i = 0; i < 3; i++) {
        int node = nodeBase + ty * 3 + i;
        if (node < NN) ((float4*)g_h2)[node * 16 + tx] = acc[i];
    }
    float4 av = ((const float4*)as2)[tx];
    float4 dv = ((const float4*)ad2)[tx];
    float ps[3], pd[3];
#pragma unroll
    for (int i = 0; i < 3; i++) {
        ps[i] = acc[i].x * av.x + acc[i].y * av.y + acc[i].z * av.z + acc[i].w * av.w;
        pd[i] = acc[i].x * dv.x + acc[i].y * dv.y + acc[i].z * dv.z + acc[i].w * dv.w;
    }
#pragma unroll
    for (int off = 8; off; off >>= 1) {
#pragma unroll
        for (int i = 0; i < 3; i++) {
            ps[i] += __shfl_xor_sync(0xffffffffu, ps[i], off);
            pd[i] += __shfl_xor_sync(0xffffffffu, pd[i], off);
        }
    }
    if (tx == 0) {
#pragma unroll
        for (int i = 0; i < 3; i++) {
            int node = nodeBase + ty * 3 + i;
            if (node < NN) { g_ssrc2[node] = ps[i]; g_sdst2[node] = pd[i]; }
        }
    }
}

// ---------------- fused softmax + aggregation (2-pass, deferred norm) ----------

// warp per dst node, layer1 (4 heads, 256 feature cols)
__global__ void __launch_bounds__(256) k_agg1(const float* __restrict__ b1) {
    int n = (blockIdx.x * blockDim.x + threadIdx.x) >> 5;
    int lane = threadIdx.x & 31;
    if (n >= NN) return;
    int o0 = g_off[n], deg = g_off[n + 1] - o0;
    float4 ep = *((const float4*)g_eproj);
    float4 sd = ((const float4*)g_sdst1)[n];

    // pass A: alpha (leaky relu), per-head max; store PRE-EXP logits
    float4 mx = make_float4(-1e30f, -1e30f, -1e30f, -1e30f);
    for (int i = lane; i < deg; i += 32) {
        int p = o0 + i;
        float a = g_eattr[p];
        int s = g_srcs[p];
        float4 ss = ((const float4*)g_ssrc1)[s];
        float4 al;
        al.x = ss.x + sd.x + a * ep.x;
        al.y = ss.y + sd.y + a * ep.y;
        al.z = ss.z + sd.z + a * ep.z;
        al.w = ss.w + sd.w + a * ep.w;
        al.x = al.x > 0.f ? al.x : 0.2f * al.x;
        al.y = al.y > 0.f ? al.y : 0.2f * al.y;
        al.z = al.z > 0.f ? al.z : 0.2f * al.z;
        al.w = al.w > 0.f ? al.w : 0.2f * al.w;
        g_alpha1[p] = al;
        mx.x = fmaxf(mx.x, al.x); mx.y = fmaxf(mx.y, al.y);
        mx.z = fmaxf(mx.z, al.z); mx.w = fmaxf(mx.w, al.w);
    }
#pragma unroll
    for (int off = 16; off; off >>= 1) {
        mx.x = fmaxf(mx.x, __shfl_xor_sync(0xffffffffu, mx.x, off));
        mx.y = fmaxf(mx.y, __shfl_xor_sync(0xffffffffu, mx.y, off));
        mx.z = fmaxf(mx.z, __shfl_xor_sync(0xffffffffu, mx.z, off));
        mx.w = fmaxf(mx.w, __shfl_xor_sync(0xffffffffu, mx.w, off));
    }
    __syncwarp();

    // pass B: gather with exp-on-the-fly; every lane walks all edges, so the
    // per-lane side-sum se equals the full per-head denominator. Normalize at end.
    int h = lane >> 3;
    float mxh = (h == 0) ? mx.x : (h == 1) ? mx.y : (h == 2) ? mx.z : mx.w;
    float4 acc0 = make_float4(0.f, 0.f, 0.f, 0.f);
    float4 acc1 = make_float4(0.f, 0.f, 0.f, 0.f);
    float se = 0.f;
    int i = 0;
    for (; i + 2 <= deg; i += 2) {
        int p0 = o0 + i, p1 = o0 + i + 1;
        float4 a0 = g_alpha1[p0];
        float4 a1 = g_alpha1[p1];
        int s0 = g_srcs[p0];
        int s1 = g_srcs[p1];
        float l0 = (h == 0) ? a0.x : (h == 1) ? a0.y : (h == 2) ? a0.z : a0.w;
        float l1 = (h == 0) ? a1.x : (h == 1) ? a1.y : (h == 2) ? a1.z : a1.w;
        float w0 = __expf(l0 - mxh);
        float w1 = __expf(l1 - mxh);
        se += w0 + w1;
        const float4* r0 = (const float4*)g_h1 + s0 * 64;
        const float4* r1 = (const float4*)g_h1 + s1 * 64;
        float4 v00 = r0[lane * 2], v01 = r0[lane * 2 + 1];
        float4 v10 = r1[lane * 2], v11 = r1[lane * 2 + 1];
        acc0.x += w0 * v00.x; acc0.y += w0 * v00.y; acc0.z += w0 * v00.z; acc0.w += w0 * v00.w;
        acc1.x += w0 * v01.x; acc1.y += w0 * v01.y; acc1.z += w0 * v01.z; acc1.w += w0 * v01.w;
        acc0.x += w1 * v10.x; acc0.y += w1 * v10.y; acc0.z += w1 * v10.z; acc0.w += w1 * v10.w;
        acc1.x += w1 * v11.x; acc1.y += w1 * v11.y; acc1.z += w1 * v11.z; acc1.w += w1 * v11.w;
    }
    if (i < deg) {
        int p = o0 + i;
        float4 a0 = g_alpha1[p];
        int s = g_srcs[p];
        float l0 = (h == 0) ? a0.x : (h == 1) ? a0.y : (h == 2) ? a0.z : a0.w;
        float w0 = __expf(l0 - mxh);
        se += w0;
        const float4* row = (const float4*)g_h1 + s * 64;
        float4 v0 = row[lane * 2], v1 = row[lane * 2 + 1];
        acc0.x += w0 * v0.x; acc0.y += w0 * v0.y; acc0.z += w0 * v0.z; acc0.w += w0 * v0.w;
        acc1.x += w0 * v1.x; acc1.y += w0 * v1.y; acc1.z += w0 * v1.z; acc1.w += w0 * v1.w;
    }
    float inv = 1.f / (se + 1e-16f);
    acc0.x *= inv; acc0.y *= inv; acc0.z *= inv; acc0.w *= inv;
    acc1.x *= inv; acc1.y *= inv; acc1.z *= inv; acc1.w *= inv;
    float4 bb0 = ((const float4*)b1)[lane * 2], bb1 = ((const float4*)b1)[lane * 2 + 1];
    acc0.x += bb0.x; acc0.y += bb0.y; acc0.z += bb0.z; acc0.w += bb0.w;
    acc1.x += bb1.x; acc1.y += bb1.y; acc1.z += bb1.z; acc1.w += bb1.w;
    acc0.x = acc0.x > 0.f ? acc0.x : (__expf(acc0.x) - 1.f);
    acc0.y = acc0.y > 0.f ? acc0.y : (__expf(acc0.y) - 1.f);
    acc0.z = acc0.z > 0.f ? acc0.z : (__expf(acc0.z) - 1.f);
    acc0.w = acc0.w > 0.f ? acc0.w : (__expf(acc0.w) - 1.f);
    acc1.x = acc1.x > 0.f ? acc1.x : (__expf(acc1.x) - 1.f);
    acc1.y = acc1.y > 0.f ? acc1.y : (__expf(acc1.y) - 1.f);
    acc1.z = acc1.z > 0.f ? acc1.z : (__expf(acc1.z) - 1.f);
    acc1.w = acc1.w > 0.f ? acc1.w : (__expf(acc1.w) - 1.f);
    float4* orow = (float4*)g_out1 + n * 64;
    orow[lane * 2] = acc0;
    orow[lane * 2 + 1] = acc1;
}

// warp per dst node, layer2 (1 head, 64 cols) -> final output + bias2
__global__ void __launch_bounds__(256) k_agg2(const float* __restrict__ b2,
                                              float* __restrict__ dout) {
    int n = (blockIdx.x * blockDim.x + threadIdx.x) >> 5;
    int lane = threadIdx.x & 31;
    if (n >= NN) return;
    int o0 = g_off[n], deg = g_off[n + 1] - o0;
    float ep = g_eproj[4];
    float sdn = g_sdst2[n];

    float mx = -1e30f;
    for (int i = lane; i < deg; i += 32) {
        int p = o0 + i;
        float a = g_eattr[p];
        int s = g_srcs[p];
        float al = g_ssrc2[s] + sdn + a * ep;
        al = al > 0.f ? al : 0.2f * al;
        g_alpha2[p] = al;
        mx = fmaxf(mx, al);
    }
#pragma unroll
    for (int off = 16; off; off >>= 1) mx = fmaxf(mx, __shfl_xor_sync(0xffffffffu, mx, off));
    __syncwarp();

    float2 acc = make_float2(0.f, 0.f);
    float se = 0.f;
    int i = 0;
    for (; i + 2 <= deg; i += 2) {
        int p0 = o0 + i, p1 = o0 + i + 1;
        float w0 = __expf(g_alpha2[p0] - mx);
        float w1 = __expf(g_alpha2[p1] - mx);
        int s0 = g_srcs[p0];
        int s1 = g_srcs[p1];
        se += w0 + w1;
        float2 v0 = ((const float2*)(g_h2 + s0 * 64))[lane];
        float2 v1 = ((const float2*)(g_h2 + s1 * 64))[lane];
        acc.x += w0 * v0.x + w1 * v1.x;
        acc.y += w0 * v0.y + w1 * v1.y;
    }
    if (i < deg) {
        int p = o0 + i;
        float w0 = __expf(g_alpha2[p] - mx);
        int s = g_srcs[p];
        se += w0;
        float2 v = ((const float2*)(g_h2 + s * 64))[lane];
        acc.x += w0 * v.x;
        acc.y += w0 * v.y;
    }
    float inv = 1.f / (se + 1e-16f);
    float2 bb = ((const float2*)b2)[lane];
    ((float2*)(dout + n * 64))[lane] = make_float2(acc.x * inv + bb.x, acc.y * inv + bb.y);
}

// ---------------- launch ----------------
extern "C" void kernel_launch(void* const* d_in, const int* in_sizes, int n_in,
                              void* d_out, int out_size) {
    const float* x   = (const float*)d_in[0];
    const int*   ei  = (const int*)d_in[1];
    const float* ea  = (const float*)d_in[2];
    const float* W1  = (const float*)d_in[3];
    const float* We1 = (const float*)d_in[4];
    const float* as1 = (const float*)d_in[5];
    const float* ad1 = (const float*)d_in[6];
    const float* ae1 = (const float*)d_in[7];
    const float* b1  = (const float*)d_in[8];
    const float* W2  = (const float*)d_in[9];
    const float* We2 = (const float*)d_in[10];
    const float* as2 = (const float*)d_in[11];
    const float* ad2 = (const float*)d_in[12];
    const float* ae2 = (const float*)d_in[13];
    const float* b2  = (const float*)d_in[14];
    float* dout = (float*)d_out;

    const int* src = ei;
    const int* dst = ei + NE;

    const int WPB = 8;                         // warps (nodes) per 256-thread block
    const int NB  = (NN + WPB - 1) / WPB;      // 6250

    // Try to fork k_gemm1 (independent of the CSR chain) onto a second stream.
    cudaStream_t s2 = 0;
    cudaEvent_t evFork = 0, evJoin = 0;
    bool fork_ok =
        (cudaStreamCreateWithFlags(&s2, cudaStreamNonBlocking) == cudaSuccess);
    if (fork_ok) fork_ok = (cudaEventCreateWithFlags(&evFork, cudaEventDisableTiming) == cudaSuccess);
    if (fork_ok) fork_ok = (cudaEventCreateWithFlags(&evJoin, cudaEventDisableTiming) == cudaSuccess);

    if (fork_ok) {
        fork_ok = (cudaEventRecord(evFork, 0) == cudaSuccess) &&
                  (cudaStreamWaitEvent(s2, evFork, 0) == cudaSuccess);
    }

    if (fork_ok) {
        // branch 1 (s2): layer1 GEMM
        k_gemm1<<<(NN + 31) / 32, 256, 0, s2>>>(x, W1, as1, ad1);
        cudaEventRecord(evJoin, s2);
        // branch 2 (origin stream): CSR build
        k_init<<<(NN + 255) / 256, 256>>>(We1, ae1, We2, ae2);
        k_hist<<<(NE + 255) / 256, 256>>>(dst, ea);
        k_scan1<<<SB, 256>>>();
        k_scan2<<<1, 256>>>();
        k_scan3<<<SB, 256>>>();
        k_fill<<<(ET + 255) / 256, 256>>>(src, dst, ea);
        cudaStreamWaitEvent(0, evJoin, 0);     // join
    } else {
        // serial fallback
        k_init<<<(NN + 255) / 256, 256>>>(We1, ae1, We2, ae2);
        k_hist<<<(NE + 255) / 256, 256>>>(dst, ea);
        k_scan1<<<SB, 256>>>();
        k_scan2<<<1, 256>>>();
        k_scan3<<<SB, 256>>>();
        k_fill<<<(ET + 255) / 256, 256>>>(src, dst, ea);
        k_gemm1<<<(NN + 31) / 32, 256>>>(x, W1, as1, ad1);
    }

    k_agg1<<<NB, 256>>>(b1);
    k_gemm2<<<(NN + 47) / 48, 256>>>(W2, as2, ad2);
    k_agg2<<<NB, 256>>>(b2, dout);

    if (evFork) cudaEventDestroy(evFork);
    if (evJoin) cudaEventDestroy(evJoin);
    if (s2) cudaStreamDestroy(s2);
}

// round 10
// speedup vs baseline: 1.8278x; 1.1230x over previous
#include <cuda_runtime.h>
#include <math.h>

// Problem constants
#define NN 50000          // nodes
#define NE 500000         // original edges
#define ET (NE + NN)      // edges + self loops = 550000
#define D1 256            // layer1 out (4 heads x 64)
#define C2 64
#define IND 128
#define SB  ((NN + 255) / 256)   // scan blocks = 196

typedef unsigned long long ull;

// ---------------- device scratch (static, no allocation) ----------------
__device__ float  g_h1[NN * D1];        // layer1 projected features
__device__ float  g_out1[NN * D1];      // layer1 aggregated+elu output
__device__ float  g_h2[NN * C2];        // layer2 projected features
__device__ float  g_ssrc1[NN * 4];
__device__ float  g_sdst1[NN * 4];
__device__ float  g_ssrc2[NN];
__device__ float  g_sdst2[NN];
__device__ float4 g_alpha1[ET];         // pre-exp attention logits (leaky-relu'd)
__device__ float  g_alpha2[ET];
__device__ float  g_loop[NN];
__device__ __align__(16) float g_eproj[8];   // [0..3]=layer1 heads, [4]=layer2
// CSR
__device__ int    g_deg[NN];
__device__ int    g_off[NN + 1];
__device__ int    g_cur[NN];
__device__ int    g_srcs[ET];
__device__ float  g_eattr[ET];          // edge attr (loop attr for self loops)
__device__ float  g_sum[NN];
__device__ int    g_bsum[SB];
__device__ int    g_boff[SB];

// ---------------- f32x2 packed math helpers ----------------
__device__ __forceinline__ ull pack2(float lo, float hi) {
    ull r;
    asm("mov.b64 %0, {%1, %2};" : "=l"(r) : "f"(lo), "f"(hi));
    return r;
}
__device__ __forceinline__ void fma2(ull& d, ull a, ull b) {
    asm("fma.rn.f32x2 %0, %1, %2, %0;" : "+l"(d) : "l"(a), "l"(b));
}
__device__ __forceinline__ float2 unpack2(ull v) {
    float2 r;
    asm("mov.b64 {%0, %1}, %2;" : "=f"(r.x), "=f"(r.y) : "l"(v));
    return r;
}

// ---------------- init: deg=1 (self loop), sum=0, eproj scalars ----------------
__global__ void k_init(const float* __restrict__ We1, const float* __restrict__ ae1,
                       const float* __restrict__ We2, const float* __restrict__ ae2) {
    int i = blockIdx.x * blockDim.x + threadIdx.x;
    if (i < NN) { g_deg[i] = 1; g_sum[i] = 0.f; }
    if (blockIdx.x == 0) {
        __shared__ float sm[256];
        int t = threadIdx.x;
        sm[t] = We1[t] * ae1[t];
        __syncthreads();
        if (t < 4) {
            float s = 0.f;
            for (int j = 0; j < 64; j++) s += sm[t * 64 + j];
            g_eproj[t] = s;
        }
        __syncthreads();
        if (t < 64) sm[t] = We2[t] * ae2[t];
        __syncthreads();
        if (t == 0) {
            float s = 0.f;
            for (int j = 0; j < 64; j++) s += sm[j];
            g_eproj[4] = s;
        }
    }
}

__global__ void k_hist(const int* __restrict__ dst, const float* __restrict__ ea) {
    int e = blockIdx.x * blockDim.x + threadIdx.x;
    if (e >= NE) return;
    int d = dst[e];
    atomicAdd(&g_deg[d], 1);
    atomicAdd(&g_sum[d], ea[e]);
}

// ---------------- 3-phase decoupled scan (coalesced) ----------------

__global__ void k_scan1() {
    int b = blockIdx.x, t = threadIdx.x;
    int i = b * 256 + t;
    int v = (i < NN) ? g_deg[i] : 0;
#pragma unroll
    for (int off = 16; off; off >>= 1) v += __shfl_xor_sync(0xffffffffu, v, off);
    __shared__ int ws[8];
    if ((t & 31) == 0) ws[t >> 5] = v;
    __syncthreads();
    if (t == 0) {
        int s = 0;
#pragma unroll
        for (int j = 0; j < 8; j++) s += ws[j];
        g_bsum[b] = s;
    }
}

__global__ void k_scan2() {
    __shared__ int sm[256];
    int t = threadIdx.x;
    int v = (t < SB) ? g_bsum[t] : 0;
    sm[t] = v;
    __syncthreads();
    for (int off = 1; off < 256; off <<= 1) {
        int y = (t >= off) ? sm[t - off] : 0;
        __syncthreads();
        sm[t] += y;
        __syncthreads();
    }
    if (t < SB) g_boff[t] = sm[t] - v;
    if (t == 0) g_off[NN] = ET;      // total degree is always NE + NN
}

__global__ void k_scan3() {
    int b = blockIdx.x, t = threadIdx.x;
    int lane = t & 31, w = t >> 5;
    int i = b * 256 + t;
    int v = (i < NN) ? g_deg[i] : 0;
    int x = v;
#pragma unroll
    for (int off = 1; off < 32; off <<= 1) {
        int y = __shfl_up_sync(0xffffffffu, x, off);
        if (lane >= off) x += y;
    }
    __shared__ int ws[8];
    if (lane == 31) ws[w] = x;
    __syncthreads();
    if (t == 0) {
        int run = 0;
#pragma unroll
        for (int j = 0; j < 8; j++) { int tmp = ws[j]; ws[j] = run; run += tmp; }
    }
    __syncthreads();
    int excl = (x - v) + ws[w] + g_boff[b];
    if (i < NN) {
        g_off[i] = excl;
        g_cur[i] = excl;
        g_loop[i] = g_sum[i] / fmaxf((float)(v - 1), 1.f);
    }
}

__global__ void k_fill(const int* __restrict__ src, const int* __restrict__ dst,
                       const float* __restrict__ ea) {
    int e = blockIdx.x * blockDim.x + threadIdx.x;
    if (e >= ET) return;
    int s, d; float a;
    if (e < NE) { s = src[e]; d = dst[e]; a = ea[e]; }
    else { s = e - NE; d = s; a = g_loop[s]; }
    int pos = atomicAdd(&g_cur[d], 1);
    g_srcs[pos] = s;
    g_eattr[pos] = a;
}

// ---------------- GEMM1: f32x2 node-pair packing over transposed smem ---------
// Block: 32 nodes x 256 cols. Thread: 4 node-pairs x 4 cols (16 FFMA2 = 32 FMA/k).
// xs is stored transposed [k][node] (pad 34) so a node-pair is one aligned LDS.64.
__global__ void __launch_bounds__(256) k_gemm1(const float* __restrict__ x,
                                               const float* __restrict__ W1,
                                               const float* __restrict__ as1,
                                               const float* __restrict__ ad1) {
    __shared__ __align__(16) float xs[IND * 34];     // 17.4KB, transposed + pad
    int t = threadIdx.x;
    int tx = t & 63, ty = t >> 6;
    int nodeBase = blockIdx.x * 32;
    // coalesced load + transpose (2-way bank conflict on write, acceptable)
#pragma unroll
    for (int i = 0; i < 16; i++) {
        int idx = i * 256 + t;                       // 0..4095 over 32 nodes x 128 k
        int k = idx & 127, n = idx >> 7;
        float v = (nodeBase + n < NN) ? x[nodeBase * IND + idx] : 0.f;
        xs[k * 34 + n] = v;
    }
    __syncthreads();

    ull acc[16];                                     // [pair p][col c]
#pragma unroll
    for (int i = 0; i < 16; i++) acc[i] = 0ull;
    const float4* __restrict__ W4 = (const float4*)W1;
#pragma unroll 2
    for (int k = 0; k < IND; k++) {
        float4 w = W4[k * 64 + tx];
        ull b0 = pack2(w.x, w.x);
        ull b1 = pack2(w.y, w.y);
        ull b2 = pack2(w.z, w.z);
        ull b3 = pack2(w.w, w.w);
        const ull* xrow = (const ull*)(xs + k * 34 + ty * 8);   // warp-uniform -> broadcast
#pragma unroll
        for (int p = 0; p < 4; p++) {
            ull a = xrow[p];                         // {x[n2p], x[n2p+1]}
            fma2(acc[p * 4 + 0], a, b0);
            fma2(acc[p * 4 + 1], a, b1);
            fma2(acc[p * 4 + 2], a, b2);
            fma2(acc[p * 4 + 3], a, b3);
        }
    }

    // store h1 + fused score epilogue
    float4 av = ((const float4*)as1)[tx];
    float4 dv = ((const float4*)ad1)[tx];
    float ps[8], pd[8];
#pragma unroll
    for (int p = 0; p < 4; p++) {
        float2 c0 = unpack2(acc[p * 4 + 0]);
        float2 c1 = unpack2(acc[p * 4 + 1]);
        float2 c2 = unpack2(acc[p * 4 + 2]);
        float2 c3 = unpack2(acc[p * 4 + 3]);
        int n0 = nodeBase + ty * 8 + 2 * p;
        if (n0 < NN)     ((float4*)g_h1)[n0 * 64 + tx]      = make_float4(c0.x, c1.x, c2.x, c3.x);
        if (n0 + 1 < NN) ((float4*)g_h1)[(n0 + 1) * 64 + tx] = make_float4(c0.y, c1.y, c2.y, c3.y);
        ps[2 * p]     = c0.x * av.x + c1.x * av.y + c2.x * av.z + c3.x * av.w;
        ps[2 * p + 1] = c0.y * av.x + c1.y * av.y + c2.y * av.z + c3.y * av.w;
        pd[2 * p]     = c0.x * dv.x + c1.x * dv.y + c2.x * dv.z + c3.x * dv.w;
        pd[2 * p + 1] = c0.y * dv.x + c1.y * dv.y + c2.y * dv.z + c3.y * dv.w;
    }
#pragma unroll
    for (int off = 8; off; off >>= 1) {
#pragma unroll
        for (int i = 0; i < 8; i++) {
            ps[i] += __shfl_xor_sync(0xffffffffu, ps[i], off);
            pd[i] += __shfl_xor_sync(0xffffffffu, pd[i], off);
        }
    }
    if ((tx & 15) == 0) {
        int h = tx >> 4;
#pragma unroll
        for (int i = 0; i < 8; i++) {
            int node = nodeBase + ty * 8 + i;
            if (node < NN) {
                g_ssrc1[node * 4 + h] = ps[i];
                g_sdst1[node * 4 + h] = pd[i];
            }
        }
    }
}

// GEMM2: h2 = out1 @ W2. Block: 48 nodes x 64 cols; thread: 3 nodes x 4 cols.
__global__ void __launch_bounds__(256) k_gemm2(const float* __restrict__ W2,
                                               const float* __restrict__ as2,
                                               const float* __restrict__ ad2) {
    __shared__ __align__(16) float xs[48 * D1];      // 48KB
    int t = threadIdx.x;
    int tx = t & 15, ty = t >> 4;
    int nodeBase = blockIdx.x * 48;
    const float4* xg = (const float4*)g_out1;
    float4* xs4 = (float4*)xs;
#pragma unroll
    for (int i = 0; i < 12; i++) {
        int idx = i * 256 + t;
        int gidx = nodeBase * 64 + idx;
        xs4[idx] = (gidx < NN * 64) ? xg[gidx] : make_float4(0.f, 0.f, 0.f, 0.f);
    }
    __syncthreads();
    float4 acc[3];
#pragma unroll
    for (int i = 0; i < 3; i++) acc[i] = make_float4(0.f, 0.f, 0.f, 0.f);
    const float4* __restrict__ W4 = (const float4*)W2;
    const float* xrow = xs + ty * 3 * D1;
#pragma unroll 4
    for (int k = 0; k < D1; k++) {
        float4 w = W4[k * 16 + tx];
#pragma unroll
        for (int i = 0; i < 3; i++) {
            float xv = xrow[i * D1 + k];
            acc[i].x += xv * w.x; acc[i].y += xv * w.y;
            acc[i].z += xv * w.z; acc[i].w += xv * w.w;
        }
    }
#pragma unroll
    for (int i = 0; i < 3; i++) {
        int node = nodeBase + ty * 3 + i;
        if (node < NN) ((float4*)g_h2)[node * 16 + tx] = acc[i];
    }
    float4 av = ((const float4*)as2)[tx];
    float4 dv = ((const float4*)ad2)[tx];
    float ps[3], pd[3];
#pragma unroll
    for (int i = 0; i < 3; i++) {
        ps[i] = acc[i].x * av.x + acc[i].y * av.y + acc[i].z * av.z + acc[i].w * av.w;
        pd[i] = acc[i].x * dv.x + acc[i].y * dv.y + acc[i].z * dv.z + acc[i].w * dv.w;
    }
#pragma unroll
    for (int off = 8; off; off >>= 1) {
#pragma unroll
        for (int i = 0; i < 3; i++) {
            ps[i] += __shfl_xor_sync(0xffffffffu, ps[i], off);
            pd[i] += __shfl_xor_sync(0xffffffffu, pd[i], off);
        }
    }
    if (tx == 0) {
#pragma unroll
        for (int i = 0; i < 3; i++) {
            int node = nodeBase + ty * 3 + i;
            if (node < NN) { g_ssrc2[node] = ps[i]; g_sdst2[node] = pd[i]; }
        }
    }
}

// ---------------- fused softmax + aggregation (2-pass, deferred norm) ----------

// warp per dst node, layer1 (4 heads, 256 feature cols)
__global__ void __launch_bounds__(256) k_agg1(const float* __restrict__ b1) {
    int n = (blockIdx.x * blockDim.x + threadIdx.x) >> 5;
    int lane = threadIdx.x & 31;
    if (n >= NN) return;
    int o0 = g_off[n], deg = g_off[n + 1] - o0;
    float4 ep = *((const float4*)g_eproj);
    float4 sd = ((const float4*)g_sdst1)[n];

    // pass A: alpha (leaky relu), per-head max; store PRE-EXP logits
    float4 mx = make_float4(-1e30f, -1e30f, -1e30f, -1e30f);
    for (int i = lane; i < deg; i += 32) {
        int p = o0 + i;
        float a = g_eattr[p];
        int s = g_srcs[p];
        float4 ss = ((const float4*)g_ssrc1)[s];
        float4 al;
        al.x = ss.x + sd.x + a * ep.x;
        al.y = ss.y + sd.y + a * ep.y;
        al.z = ss.z + sd.z + a * ep.z;
        al.w = ss.w + sd.w + a * ep.w;
        al.x = al.x > 0.f ? al.x : 0.2f * al.x;
        al.y = al.y > 0.f ? al.y : 0.2f * al.y;
        al.z = al.z > 0.f ? al.z : 0.2f * al.z;
        al.w = al.w > 0.f ? al.w : 0.2f * al.w;
        g_alpha1[p] = al;
        mx.x = fmaxf(mx.x, al.x); mx.y = fmaxf(mx.y, al.y);
        mx.z = fmaxf(mx.z, al.z); mx.w = fmaxf(mx.w, al.w);
    }
#pragma unroll
    for (int off = 16; off; off >>= 1) {
        mx.x = fmaxf(mx.x, __shfl_xor_sync(0xffffffffu, mx.x, off));
        mx.y = fmaxf(mx.y, __shfl_xor_sync(0xffffffffu, mx.y, off));
        mx.z = fmaxf(mx.z, __shfl_xor_sync(0xffffffffu, mx.z, off));
        mx.w = fmaxf(mx.w, __shfl_xor_sync(0xffffffffu, mx.w, off));
    }
    __syncwarp();

    // pass B: gather with exp-on-the-fly, x4 unrolled for L2 MLP
    int h = lane >> 3;
    float mxh = (h == 0) ? mx.x : (h == 1) ? mx.y : (h == 2) ? mx.z : mx.w;
    float4 acc0 = make_float4(0.f, 0.f, 0.f, 0.f);
    float4 acc1 = make_float4(0.f, 0.f, 0.f, 0.f);
    float se = 0.f;
    int i = 0;
    for (; i + 4 <= deg; i += 4) {
        int p0 = o0 + i;
        float4 a0 = g_alpha1[p0], a1 = g_alpha1[p0 + 1];
        float4 a2 = g_alpha1[p0 + 2], a3 = g_alpha1[p0 + 3];
        int s0 = g_srcs[p0], s1 = g_srcs[p0 + 1];
        int s2 = g_srcs[p0 + 2], s3 = g_srcs[p0 + 3];
        float w0 = __expf(((h == 0) ? a0.x : (h == 1) ? a0.y : (h == 2) ? a0.z : a0.w) - mxh);
        float w1 = __expf(((h == 0) ? a1.x : (h == 1) ? a1.y : (h == 2) ? a1.z : a1.w) - mxh);
        float w2 = __expf(((h == 0) ? a2.x : (h == 1) ? a2.y : (h == 2) ? a2.z : a2.w) - mxh);
        float w3 = __expf(((h == 0) ? a3.x : (h == 1) ? a3.y : (h == 2) ? a3.z : a3.w) - mxh);
        se += (w0 + w1) + (w2 + w3);
        const float4* r0 = (const float4*)g_h1 + s0 * 64;
        const float4* r1 = (const float4*)g_h1 + s1 * 64;
        const float4* r2 = (const float4*)g_h1 + s2 * 64;
        const float4* r3 = (const float4*)g_h1 + s3 * 64;
        float4 v00 = r0[lane * 2], v01 = r0[lane * 2 + 1];
        float4 v10 = r1[lane * 2], v11 = r1[lane * 2 + 1];
        float4 v20 = r2[lane * 2], v21 = r2[lane * 2 + 1];
        float4 v30 = r3[lane * 2], v31 = r3[lane * 2 + 1];
        acc0.x += w0 * v00.x; acc0.y += w0 * v00.y; acc0.z += w0 * v00.z; acc0.w += w0 * v00.w;
        acc1.x += w0 * v01.x; acc1.y += w0 * v01.y; acc1.z += w0 * v01.z; acc1.w += w0 * v01.w;
        acc0.x += w1 * v10.x; acc0.y += w1 * v10.y; acc0.z += w1 * v10.z; acc0.w += w1 * v10.w;
        acc1.x += w1 * v11.x; acc1.y += w1 * v11.y; acc1.z += w1 * v11.z; acc1.w += w1 * v11.w;
        acc0.x += w2 * v20.x; acc0.y += w2 * v20.y; acc0.z += w2 * v20.z; acc0.w += w2 * v20.w;
        acc1.x += w2 * v21.x; acc1.y += w2 * v21.y; acc1.z += w2 * v21.z; acc1.w += w2 * v21.w;
        acc0.x += w3 * v30.x; acc0.y += w3 * v30.y; acc0.z += w3 * v30.z; acc0.w += w3 * v30.w;
        acc1.x += w3 * v31.x; acc1.y += w3 * v31.y; acc1.z += w3 * v31.z; acc1.w += w3 * v31.w;
    }
    for (; i < deg; i++) {
        int p = o0 + i;
        float4 a0 = g_alpha1[p];
        int s = g_srcs[p];
        float l0 = (h == 0) ? a0.x : (h == 1) ? a0.y : (h == 2) ? a0.z : a0.w;
        float w0 = __expf(l0 - mxh);
        se += w0;
        const float4* row = (const float4*)g_h1 + s * 64;
        float4 v0 = row[lane * 2], v1 = row[lane * 2 + 1];
        acc0.x += w0 * v0.x; acc0.y += w0 * v0.y; acc0.z += w0 * v0.z; acc0.w += w0 * v0.w;
        acc1.x += w0 * v1.x; acc1.y += w0 * v1.y; acc1.z += w0 * v1.z; acc1.w += w0 * v1.w;
    }
    float inv = 1.f / (se + 1e-16f);
    acc0.x *= inv; acc0.y *= inv; acc0.z *= inv; acc0.w *= inv;
    acc1.x *= inv; acc1.y *= inv; acc1.z *= inv; acc1.w *= inv;
    float4 bb0 = ((const float4*)b1)[lane * 2], bb1 = ((const float4*)b1)[lane * 2 + 1];
    acc0.x += bb0.x; acc0.y += bb0.y; acc0.z += bb0.z; acc0.w += bb0.w;
    acc1.x += bb1.x; acc1.y += bb1.y; acc1.z += bb1.z; acc1.w += bb1.w;
    acc0.x = acc0.x > 0.f ? acc0.x : (__expf(acc0.x) - 1.f);
    acc0.y = acc0.y > 0.f ? acc0.y : (__expf(acc0.y) - 1.f);
    acc0.z = acc0.z > 0.f ? acc0.z : (__expf(acc0.z) - 1.f);
    acc0.w = acc0.w > 0.f ? acc0.w : (__expf(acc0.w) - 1.f);
    acc1.x = acc1.x > 0.f ? acc1.x : (__expf(acc1.x) - 1.f);
    acc1.y = acc1.y > 0.f ? acc1.y : (__expf(acc1.y) - 1.f);
    acc1.z = acc1.z > 0.f ? acc1.z : (__expf(acc1.z) - 1.f);
    acc1.w = acc1.w > 0.f ? acc1.w : (__expf(acc1.w) - 1.f);
    float4* orow = (float4*)g_out1 + n * 64;
    orow[lane * 2] = acc0;
    orow[lane * 2 + 1] = acc1;
}

// warp per dst node, layer2 (1 head, 64 cols) -> final output + bias2
__global__ void __launch_bounds__(256) k_agg2(const float* __restrict__ b2,
                                              float* __restrict__ dout) {
    int n = (blockIdx.x * blockDim.x + threadIdx.x) >> 5;
    int lane = threadIdx.x & 31;
    if (n >= NN) return;
    int o0 = g_off[n], deg = g_off[n + 1] - o0;
    float ep = g_eproj[4];
    float sdn = g_sdst2[n];

    float mx = -1e30f;
    for (int i = lane; i < deg; i += 32) {
        int p = o0 + i;
        float a = g_eattr[p];
        int s = g_srcs[p];
        float al = g_ssrc2[s] + sdn + a * ep;
        al = al > 0.f ? al : 0.2f * al;
        g_alpha2[p] = al;
        mx = fmaxf(mx, al);
    }
#pragma unroll
    for (int off = 16; off; off >>= 1) mx = fmaxf(mx, __shfl_xor_sync(0xffffffffu, mx, off));
    __syncwarp();

    float2 acc = make_float2(0.f, 0.f);
    float se = 0.f;
    int i = 0;
    for (; i + 4 <= deg; i += 4) {
        int p0 = o0 + i;
        float w0 = __expf(g_alpha2[p0] - mx);
        float w1 = __expf(g_alpha2[p0 + 1] - mx);
        float w2 = __expf(g_alpha2[p0 + 2] - mx);
        float w3 = __expf(g_alpha2[p0 + 3] - mx);
        int s0 = g_srcs[p0], s1 = g_srcs[p0 + 1];
        int s2 = g_srcs[p0 + 2], s3 = g_srcs[p0 + 3];
        se += (w0 + w1) + (w2 + w3);
        float2 v0 = ((const float2*)(g_h2 + s0 * 64))[lane];
        float2 v1 = ((const float2*)(g_h2 + s1 * 64))[lane];
        float2 v2 = ((const float2*)(g_h2 + s2 * 64))[lane];
        float2 v3 = ((const float2*)(g_h2 + s3 * 64))[lane];
        acc.x += w0 * v0.x + w1 * v1.x + w2 * v2.x + w3 * v3.x;
        acc.y += w0 * v0.y + w1 * v1.y + w2 * v2.y + w3 * v3.y;
    }
    for (; i < deg; i++) {
        int p = o0 + i;
        float w0 = __expf(g_alpha2[p] - mx);
        int s = g_srcs[p];
        se += w0;
        float2 v = ((const float2*)(g_h2 + s * 64))[lane];
        acc.x += w0 * v.x;
        acc.y += w0 * v.y;
    }
    float inv = 1.f / (se + 1e-16f);
    float2 bb = ((const float2*)b2)[lane];
    ((float2*)(dout + n * 64))[lane] = make_float2(acc.x * inv + bb.x, acc.y * inv + bb.y);
}

// ---------------- launch ----------------
extern "C" void kernel_launch(void* const* d_in, const int* in_sizes, int n_in,
                              void* d_out, int out_size) {
    const float* x   = (const float*)d_in[0];
    const int*   ei  = (const int*)d_in[1];
    const float* ea  = (const float*)d_in[2];
    const float* W1  = (const float*)d_in[3];
    const float* We1 = (const float*)d_in[4];
    const float* as1 = (const float*)d_in[5];
    const float* ad1 = (const float*)d_in[6];
    const float* ae1 = (const float*)d_in[7];
    const float* b1  = (const float*)d_in[8];
    const float* W2  = (const float*)d_in[9];
    const float* We2 = (const float*)d_in[10];
    const float* as2 = (const float*)d_in[11];
    const float* ad2 = (const float*)d_in[12];
    const float* ae2 = (const float*)d_in[13];
    const float* b2  = (const float*)d_in[14];
    float* dout = (float*)d_out;

    const int* src = ei;
    const int* dst = ei + NE;

    const int WPB = 8;                         // warps (nodes) per 256-thread block
    const int NB  = (NN + WPB - 1) / WPB;      // 6250

    // Fork k_gemm1 (independent of the CSR chain) onto a second stream.
    cudaStream_t s2 = 0;
    cudaEvent_t evFork = 0, evJoin = 0;
    bool fork_ok =
        (cudaStreamCreateWithFlags(&s2, cudaStreamNonBlocking) == cudaSuccess);
    if (fork_ok) fork_ok = (cudaEventCreateWithFlags(&evFork, cudaEventDisableTiming) == cudaSuccess);
    if (fork_ok) fork_ok = (cudaEventCreateWithFlags(&evJoin, cudaEventDisableTiming) == cudaSuccess);

    if (fork_ok) {
        fork_ok = (cudaEventRecord(evFork, 0) == cudaSuccess) &&
                  (cudaStreamWaitEvent(s2, evFork, 0) == cudaSuccess);
    }

    if (fork_ok) {
        k_gemm1<<<(NN + 31) / 32, 256, 0, s2>>>(x, W1, as1, ad1);
        cudaEventRecord(evJoin, s2);
        k_init<<<(NN + 255) / 256, 256>>>(We1, ae1, We2, ae2);
        k_hist<<<(NE + 255) / 256, 256>>>(dst, ea);
        k_scan1<<<SB, 256>>>();
        k_scan2<<<1, 256>>>();
        k_scan3<<<SB, 256>>>();
        k_fill<<<(ET + 255) / 256, 256>>>(src, dst, ea);
        cudaStreamWaitEvent(0, evJoin, 0);     // join
    } else {
        k_init<<<(NN + 255) / 256, 256>>>(We1, ae1, We2, ae2);
        k_hist<<<(NE + 255) / 256, 256>>>(dst, ea);
        k_scan1<<<SB, 256>>>();
        k_scan2<<<1, 256>>>();
        k_scan3<<<SB, 256>>>();
        k_fill<<<(ET + 255) / 256, 256>>>(src, dst, ea);
        k_gemm1<<<(NN + 31) / 32, 256>>>(x, W1, as1, ad1);
    }

    k_agg1<<<NB, 256>>>(b1);
    k_gemm2<<<(NN + 47) / 48, 256>>>(W2, as2, ad2);
    k_agg2<<<NB, 256>>>(b2, dout);

    if (evFork) cudaEventDestroy(evFork);
    if (evJoin) cudaEventDestroy(evJoin);
    if (s2) cudaStreamDestroy(s2);
}